// round 6
// baseline (speedup 1.0000x reference)
#include <cuda_runtime.h>
#include <cuda_bf16.h>
#include <cuda_fp16.h>
#include <cstdint>

// Problem constants
#define Bsz 2
#define Sl  2048
#define Dm  768
#define Iw  1536
#define Nst 16
#define Rr  48
#define Ms  (Bsz * Sl)          // 4096 rows
#define TWO_I (2 * Iw)          // 3072

// ---------------------------------------------------------------------------
// Scratch (device globals)
// ---------------------------------------------------------------------------
__device__ float g_proj[(size_t)Ms * TWO_I];
__device__ float g_h   [(size_t)Ms * Iw];
__device__ float g_ssm [(size_t)Ms * (Rr + 2 * Nst)];
__device__ float g_dt  [(size_t)Ms * Iw];

__device__ __half g_x16 [(size_t)Ms * Dm];
__device__ __half g_w1hi[(size_t)TWO_I * Dm], g_w1lo[(size_t)TWO_I * Dm];
__device__ __half g_y16 [(size_t)Ms * Iw];
__device__ __half g_w2hi[(size_t)Dm * Iw],    g_w2lo[(size_t)Dm * Iw];

// ---------------------------------------------------------------------------
// Helpers
// ---------------------------------------------------------------------------
__device__ __forceinline__ uint32_t smem_u32(const void* p) {
    uint32_t a;
    asm("{ .reg .u64 t; cvta.to.shared.u64 t, %1; cvt.u32.u64 %0, t; }" : "=r"(a) : "l"(p));
    return a;
}
__device__ __forceinline__ void cp16(uint32_t saddr, const void* gsrc) {
    asm volatile("cp.async.cg.shared.global [%0], [%1], 16;" :: "r"(saddr), "l"(gsrc));
}
#define CP_COMMIT() asm volatile("cp.async.commit_group;" ::: "memory")
#define CP_WAIT(n)  asm volatile("cp.async.wait_group %0;" :: "n"(n) : "memory")

__device__ __forceinline__ void ldm_x4(uint32_t* r, uint32_t addr) {
    asm volatile("ldmatrix.sync.aligned.m8n8.x4.shared.b16 {%0,%1,%2,%3}, [%4];"
                 : "=r"(r[0]), "=r"(r[1]), "=r"(r[2]), "=r"(r[3]) : "r"(addr));
}
__device__ __forceinline__ void ldm_x2(uint32_t* r, uint32_t addr) {
    asm volatile("ldmatrix.sync.aligned.m8n8.x2.shared.b16 {%0,%1}, [%2];"
                 : "=r"(r[0]), "=r"(r[1]) : "r"(addr));
}
__device__ __forceinline__ void mma16816(float* c, const uint32_t* a, const uint32_t* b) {
    asm volatile("mma.sync.aligned.m16n8k16.row.col.f32.f16.f16.f32 "
                 "{%0,%1,%2,%3}, {%4,%5,%6,%7}, {%8,%9}, {%0,%1,%2,%3};"
                 : "+f"(c[0]), "+f"(c[1]), "+f"(c[2]), "+f"(c[3])
                 : "r"(a[0]), "r"(a[1]), "r"(a[2]), "r"(a[3]), "r"(b[0]), "r"(b[1]));
}

// ---------------------------------------------------------------------------
// HMMA fp16x2 GEMM: C[M,N] = A16[M,K] @ (Whi+Wlo)[N,K]^T
// 128x128 CTA tile, BK=32, 256 threads, 2-stage cp.async, 2 CTAs/SM.
// ---------------------------------------------------------------------------
#define STRD 40
#define TILE_B (128 * STRD * 2)            // 10240 B per matrix tile
#define STAGE_B (3 * TILE_B)               // A, Whi, Wlo            (30720)
#define SMEM_B (2 * STAGE_B)               // 61440

__global__ __launch_bounds__(256, 2)
void hmma_f16x2(const __half* __restrict__ A16,
                const __half* __restrict__ Whi, const __half* __restrict__ Wlo,
                float* __restrict__ C, int M, int N, int K)
{
    extern __shared__ __align__(16) char smem[];
    const uint32_t sb = smem_u32(smem);
    const int tid = threadIdx.x;
    const int wid = tid >> 5, lane = tid & 31;
    const int warp_m = wid >> 2, warp_n = wid & 3;
    const int bm = blockIdx.y * 128, bn = blockIdx.x * 128;

    // per stage: 3 mats x 128 rows x 4 16B-chunks = 1536 slots / 256 thr = 6
    auto load_stage = [&](int st, int k0) {
#pragma unroll
        for (int l = 0; l < 6; l++) {
            int v = tid + l * 256;
            int mat = v >> 9;
            int rem = v & 511;
            int row = rem >> 2;
            int c16 = rem & 3;
            const __half* src;
            if (mat == 0)      src = A16 + (size_t)(bm + row) * K + k0 + c16 * 8;
            else if (mat == 1) src = Whi + (size_t)(bn + row) * K + k0 + c16 * 8;
            else               src = Wlo + (size_t)(bn + row) * K + k0 + c16 * 8;
            uint32_t dst = sb + st * STAGE_B + mat * TILE_B + (row * STRD + c16 * 8) * 2;
            cp16(dst, src);
        }
        CP_COMMIT();
    };

    float acc[4][4][4];
#pragma unroll
    for (int i = 0; i < 4; i++)
#pragma unroll
        for (int j = 0; j < 4; j++)
#pragma unroll
            for (int k = 0; k < 4; k++) acc[i][j][k] = 0.f;

    const int nch = K >> 5;
    load_stage(0, 0);

    const int a_r = warp_m * 64 + (lane & 15);
    const int a_k = (lane >> 4) * 8;
    const int b_r = warp_n * 32 + (lane & 7);
    const int b_k = ((lane >> 3) & 1) * 8;

    for (int ch = 0; ch < nch; ch++) {
        const int st = ch & 1;
        if (ch + 1 < nch) load_stage(st ^ 1, (ch + 1) << 5);
        if (ch + 1 < nch) { CP_WAIT(1); } else { CP_WAIT(0); }
        __syncthreads();

        const uint32_t aB   = sb + st * STAGE_B;
        const uint32_t wHiB = aB + TILE_B;
        const uint32_t wLoB = aB + 2 * TILE_B;

#pragma unroll
        for (int kk = 0; kk < 2; kk++) {
            uint32_t a[4][4], bhi[4][2], blo[4][2];
#pragma unroll
            for (int mt = 0; mt < 4; mt++)
                ldm_x4(a[mt], aB + ((a_r + mt * 16) * STRD + a_k + kk * 16) * 2);
#pragma unroll
            for (int nt = 0; nt < 4; nt++)
                ldm_x2(bhi[nt], wHiB + ((b_r + nt * 8) * STRD + b_k + kk * 16) * 2);
#pragma unroll
            for (int mt = 0; mt < 4; mt++)
#pragma unroll
                for (int nt = 0; nt < 4; nt++)
                    mma16816(acc[mt][nt], a[mt], bhi[nt]);
#pragma unroll
            for (int nt = 0; nt < 4; nt++)
                ldm_x2(blo[nt], wLoB + ((b_r + nt * 8) * STRD + b_k + kk * 16) * 2);
#pragma unroll
            for (int mt = 0; mt < 4; mt++)
#pragma unroll
                for (int nt = 0; nt < 4; nt++)
                    mma16816(acc[mt][nt], a[mt], blo[nt]);
        }
        __syncthreads();
    }

    const int er = bm + warp_m * 64 + (lane >> 2);
    const int ec = bn + warp_n * 32 + (lane & 3) * 2;
#pragma unroll
    for (int mt = 0; mt < 4; mt++)
#pragma unroll
        for (int nt = 0; nt < 4; nt++) {
            int r = er + mt * 16;
            int c = ec + nt * 8;
            *(float2*)&C[(size_t)r * N + c]       = make_float2(acc[mt][nt][0], acc[mt][nt][1]);
            *(float2*)&C[(size_t)(r + 8) * N + c] = make_float2(acc[mt][nt][2], acc[mt][nt][3]);
        }
}

// ---------------------------------------------------------------------------
// fp32 -> fp16 convert (activations) and fp32 -> (hi,lo) fp16 split (weights)
// ---------------------------------------------------------------------------
__global__ __launch_bounds__(256)
void conv_f16(const float* __restrict__ in, __half* __restrict__ out, int n4)
{
    int i = blockIdx.x * 256 + threadIdx.x;
    if (i >= n4) return;
    float4 v = ((const float4*)in)[i];
    __half2* op = (__half2*)(out + (size_t)i * 4);
    op[0] = __floats2half2_rn(v.x, v.y);
    op[1] = __floats2half2_rn(v.z, v.w);
}

__global__ __launch_bounds__(256)
void split_f16(const float* __restrict__ in, __half* __restrict__ hi,
               __half* __restrict__ lo, int n4)
{
    int i = blockIdx.x * 256 + threadIdx.x;
    if (i >= n4) return;
    float4 v = ((const float4*)in)[i];
    __half h0 = __float2half_rn(v.x), h1 = __float2half_rn(v.y);
    __half h2 = __float2half_rn(v.z), h3 = __float2half_rn(v.w);
    __half2* hp = (__half2*)(hi + (size_t)i * 4);
    hp[0] = __half2(h0, h1);
    hp[1] = __half2(h2, h3);
    __half2* lp = (__half2*)(lo + (size_t)i * 4);
    lp[0] = __half2(__float2half_rn(v.x - __half2float(h0)),
                    __float2half_rn(v.y - __half2float(h1)));
    lp[1] = __half2(__float2half_rn(v.z - __half2float(h2)),
                    __float2half_rn(v.w - __half2float(h3)));
}

// ---------------------------------------------------------------------------
// fp32 tiled SGEMM (small GEMMs)
// ---------------------------------------------------------------------------
template<int BM, int BN, int BK, int TM, int TN, int EPI>
__global__ __launch_bounds__(256)
void sgemm_nt(const float* __restrict__ A, const float* __restrict__ W,
              float* __restrict__ C, int M, int N, int K, int lda,
              const float* __restrict__ bias,
              const float* __restrict__ lastscale)
{
    constexpr int NT = (BM / TM) * (BN / TN);
    static_assert(NT == 256, "need 256 threads");
    constexpr int LA = (BM * BK) / (4 * NT);
    constexpr int LB = (BN * BK) / (4 * NT);

    __shared__ __align__(16) float As[BK][BM];
    __shared__ __align__(16) float Bs[BK][BN];

    const int tid = threadIdx.x;
    const int bm = blockIdx.y * BM;
    const int bn = blockIdx.x * BN;
    const int tx = tid % (BN / TN);
    const int ty = tid / (BN / TN);

    float acc[TM][TN];
#pragma unroll
    for (int a = 0; a < TM; a++)
#pragma unroll
        for (int b = 0; b < TN; b++) acc[a][b] = 0.f;

    for (int k0 = 0; k0 < K; k0 += BK) {
#pragma unroll
        for (int l = 0; l < LA; l++) {
            int v = tid + l * NT;
            int r = v / (BK / 4);
            int kq = (v % (BK / 4)) * 4;
            int grow = bm + r;
            float4 av = make_float4(0.f, 0.f, 0.f, 0.f);
            if (grow < M)
                av = *(const float4*)(A + (size_t)grow * lda + k0 + kq);
            As[kq + 0][r] = av.x; As[kq + 1][r] = av.y;
            As[kq + 2][r] = av.z; As[kq + 3][r] = av.w;
        }
#pragma unroll
        for (int l = 0; l < LB; l++) {
            int v = tid + l * NT;
            int r = v / (BK / 4);
            int kq = (v % (BK / 4)) * 4;
            int gcol = bn + r;
            float4 wv = make_float4(0.f, 0.f, 0.f, 0.f);
            if (gcol < N)
                wv = *(const float4*)(W + (size_t)gcol * K + k0 + kq);
            Bs[kq + 0][r] = wv.x; Bs[kq + 1][r] = wv.y;
            Bs[kq + 2][r] = wv.z; Bs[kq + 3][r] = wv.w;
        }
        __syncthreads();

#pragma unroll
        for (int k = 0; k < BK; k++) {
            float ra[TM], rb[TN];
#pragma unroll
            for (int u = 0; u < TM / 4; u++)
                *(float4*)&ra[4 * u] = *(const float4*)&As[k][ty * TM + 4 * u];
#pragma unroll
            for (int u = 0; u < TN / 4; u++)
                *(float4*)&rb[4 * u] = *(const float4*)&Bs[k][tx * TN + 4 * u];
#pragma unroll
            for (int a = 0; a < TM; a++)
#pragma unroll
                for (int b = 0; b < TN; b++)
                    acc[a][b] = fmaf(ra[a], rb[b], acc[a][b]);
        }
        __syncthreads();
    }

#pragma unroll
    for (int a = 0; a < TM; a++) {
        int m = bm + ty * TM + a;
        if (m >= M) continue;
        bool last = ((m % Sl) == (Sl - 1));
#pragma unroll
        for (int b = 0; b < TN; b++) {
            int n = bn + tx * TN + b;
            if (n >= N) continue;
            float v = acc[a][b];
            if (EPI == 1) {
                v += bias[n];
                v = (v > 20.f) ? v : log1pf(__expf(v));
                if (last) v *= lastscale[n];
            }
            C[(size_t)m * N + n] = v;
        }
    }
}

// ---------------------------------------------------------------------------
// Causal depthwise conv1d (K=4) + bias + SiLU — rolling-window, 16 s per block
// ---------------------------------------------------------------------------
__global__ __launch_bounds__(256)
void conv_silu2(const float* __restrict__ proj,
                const float* __restrict__ cw,
                const float* __restrict__ cb,
                float* __restrict__ h)
{
    const int blk = blockIdx.x;                 // Bsz * (Sl/16)
    const int b = blk / (Sl / 16);
    const int st = (blk % (Sl / 16)) * 16;

#pragma unroll 1
    for (int ic = 0; ic < Iw / 256; ic++) {
        const int i = ic * 256 + threadIdx.x;
        float4 w = *(const float4*)(cw + (size_t)i * 4);
        const float bia = cb[i];
        const float* base = proj + ((size_t)b * Sl + st) * TWO_I + i;
        float* outp = h + ((size_t)b * Sl + st) * Iw + i;

        float x3, x2, x1;
        if (st > 0) {
            x3 = base[-(size_t)3 * TWO_I];
            x2 = base[-(size_t)2 * TWO_I];
            x1 = base[-(size_t)1 * TWO_I];
        } else {
            x3 = x2 = x1 = 0.f;
        }
#pragma unroll
        for (int s = 0; s < 16; s++) {
            float x0 = base[(size_t)s * TWO_I];
            float acc = fmaf(w.w, x0, fmaf(w.z, x1, fmaf(w.y, x2, fmaf(w.x, x3, bia))));
            float sig = __fdividef(1.f, 1.f + __expf(-acc));
            outp[(size_t)s * Iw] = acc * sig;
            x3 = x2; x2 = x1; x1 = x0;
        }
    }
}

// ---------------------------------------------------------------------------
// Smem-staged selective scan; emits fp16 y directly.
// ---------------------------------------------------------------------------
#define SCT 64
#define NCH (Sl / SCT)

__global__ __launch_bounds__(256)
void scan_kernel2(const float* __restrict__ dt,
                  const float* __restrict__ h,
                  const float* __restrict__ ssm,
                  const float* __restrict__ proj,
                  const float* __restrict__ A_log,
                  const float* __restrict__ Dv,
                  const float* __restrict__ fg,
                  __half* __restrict__ y16)
{
    __shared__ __align__(16) float s_dt[2][SCT][16];
    __shared__ __align__(16) float s_h [2][SCT][16];
    __shared__ __align__(16) float s_g [2][SCT][16];
    __shared__ __align__(16) float s_B [2][SCT][16];
    __shared__ __align__(16) float s_C [2][SCT][16];
    __shared__ __align__(16) float s_y [SCT][16];
    __shared__ float s_D[16];

    const int tid = threadIdx.x;
    const int blk = blockIdx.x;
    const int b = blk / (Iw / 16);
    const int i0 = (blk % (Iw / 16)) * 16;

    const int ci = tid >> 4;
    const int ln = tid & 15;

    if (tid < 16) s_D[tid] = Dv[i0 + tid];

    const float An = -__expf(A_log[(size_t)(i0 + ci) * Nst + ln]);
    float state = 0.f;

    const size_t row0 = (size_t)b * Sl;
    const int lr = tid >> 2, lc = (tid & 3) * 4;

    const uint32_t a_dt = smem_u32(&s_dt[0][0][0]);
    const uint32_t a_h  = smem_u32(&s_h [0][0][0]);
    const uint32_t a_g  = smem_u32(&s_g [0][0][0]);
    const uint32_t a_B  = smem_u32(&s_B [0][0][0]);
    const uint32_t a_C  = smem_u32(&s_C [0][0][0]);
    const uint32_t stoff = SCT * 16 * 4;
    const uint32_t loff = (lr * 16 + lc) * 4;

    auto issue = [&](int st, int s0) {
        size_t r = row0 + s0 + lr;
        cp16(a_dt + st * stoff + loff, dt   + r * Iw + i0 + lc);
        cp16(a_h  + st * stoff + loff, h    + r * Iw + i0 + lc);
        cp16(a_g  + st * stoff + loff, proj + r * TWO_I + Iw + i0 + lc);
        cp16(a_B  + st * stoff + loff, ssm  + r * (Rr + 2 * Nst) + Rr + lc);
        cp16(a_C  + st * stoff + loff, ssm  + r * (Rr + 2 * Nst) + Rr + Nst + lc);
        CP_COMMIT();
    };

    issue(0, 0);

    for (int ch = 0; ch < NCH; ch++) {
        const int st = ch & 1;
        const int s0 = ch * SCT;
        if (ch + 1 < NCH) { issue(st ^ 1, s0 + SCT); CP_WAIT(1); }
        else              { CP_WAIT(0); }
        __syncthreads();

#pragma unroll 4
        for (int s = 0; s < SCT; s++) {
            float dtv = s_dt[st][s][ci];
            float hv  = s_h [st][s][ci];
            float dA  = __expf(An * dtv);
            state = fmaf(dA, state, dtv * s_B[st][s][ln] * hv);
            float part = state * s_C[st][s][ln];
            part += __shfl_xor_sync(0xffffffffu, part, 8);
            part += __shfl_xor_sync(0xffffffffu, part, 4);
            part += __shfl_xor_sync(0xffffffffu, part, 2);
            part += __shfl_xor_sync(0xffffffffu, part, 1);
            if (ln == 0) s_y[s][ci] = part;
        }
        __syncthreads();

#pragma unroll
        for (int k = 0; k < 4; k++) {
            int idx = tid + k * 256;
            int r = idx >> 4, c = idx & 15;
            float hv = s_h[st][r][c];
            float g  = s_g[st][r][c];
            float sg = g * __fdividef(1.f, 1.f + __expf(-g));
            float val = (s_y[r][c] + hv * s_D[c]) * sg;
            if (s0 + r == Sl - 1) val *= fg[i0 + c];
            y16[(row0 + s0 + r) * Iw + i0 + c] = __float2half_rn(val);
        }
        __syncthreads();
    }
}

// ---------------------------------------------------------------------------
// Launch
// ---------------------------------------------------------------------------
extern "C" void kernel_launch(void* const* d_in, const int* in_sizes, int n_in,
                              void* d_out, int out_size)
{
    const float* x          = (const float*)d_in[0];
    const float* in_proj_w  = (const float*)d_in[1];
    const float* conv_w     = (const float*)d_in[2];
    const float* conv_b     = (const float*)d_in[3];
    const float* x_proj_w   = (const float*)d_in[4];
    const float* dt_proj_w  = (const float*)d_in[5];
    const float* dt_proj_b  = (const float*)d_in[6];
    const float* A_log      = (const float*)d_in[7];
    const float* Dv         = (const float*)d_in[8];
    const float* out_proj_w = (const float*)d_in[9];
    const float* alpha      = (const float*)d_in[10];
    const float* fg         = (const float*)d_in[11];
    float* out = (float*)d_out;

    float *proj, *h, *ssm, *dt;
    cudaGetSymbolAddress((void**)&proj, g_proj);
    cudaGetSymbolAddress((void**)&h,    g_h);
    cudaGetSymbolAddress((void**)&ssm,  g_ssm);
    cudaGetSymbolAddress((void**)&dt,   g_dt);

    __half *x16, *w1hi, *w1lo, *y16, *w2hi, *w2lo;
    cudaGetSymbolAddress((void**)&x16,  g_x16);
    cudaGetSymbolAddress((void**)&w1hi, g_w1hi);
    cudaGetSymbolAddress((void**)&w1lo, g_w1lo);
    cudaGetSymbolAddress((void**)&y16,  g_y16);
    cudaGetSymbolAddress((void**)&w2hi, g_w2hi);
    cudaGetSymbolAddress((void**)&w2lo, g_w2lo);

    cudaFuncSetAttribute(hmma_f16x2, cudaFuncAttributeMaxDynamicSharedMemorySize, SMEM_B);

    // 0-2) conversions (order chosen so launch index 3 = hmma for profiling)
    {
        int n4 = (Ms * Dm) / 4;
        conv_f16<<<(n4 + 255) / 256, 256>>>(x, x16, n4);
        n4 = (TWO_I * Dm) / 4;
        split_f16<<<(n4 + 255) / 256, 256>>>(in_proj_w, w1hi, w1lo, n4);
        n4 = (Dm * Iw) / 4;
        split_f16<<<(n4 + 255) / 256, 256>>>(out_proj_w, w2hi, w2lo, n4);
    }

    // 3) in_proj (HMMA fp16x2): proj[4096,3072] = x16 @ (w1hi+w1lo)^T
    hmma_f16x2<<<dim3(TWO_I / 128, Ms / 128), 256, SMEM_B>>>(
        x16, w1hi, w1lo, proj, Ms, TWO_I, Dm);

    // 4) conv + SiLU (rolling window)
    conv_silu2<<<Bsz * (Sl / 16), 256>>>(proj, conv_w, conv_b, h);

    // 5) x_proj (fp32)
    sgemm_nt<64,64,16,4,4,0><<<dim3(2, Ms/64), 256>>>(
        h, x_proj_w, ssm, Ms, Rr + 2*Nst, Iw, Iw, nullptr, nullptr);

    // 6) dt_proj + softplus + alpha
    sgemm_nt<64,64,16,4,4,1><<<dim3(Iw/64, Ms/64), 256>>>(
        ssm, dt_proj_w, dt, Ms, Iw, Rr, Rr + 2*Nst, dt_proj_b, alpha);

    // 7) scan (emits fp16 y)
    scan_kernel2<<<(Bsz * Iw) / 16, 256>>>(dt, h, ssm, proj, A_log, Dv, fg, y16);

    // 8) out_proj (HMMA fp16x2): out[4096,768] = y16 @ (w2hi+w2lo)^T
    hmma_f16x2<<<dim3(Dm / 128, Ms / 128), 256, SMEM_B>>>(
        y16, w2hi, w2lo, out, Ms, Dm, Iw);
}

// round 7
// speedup vs baseline: 1.8371x; 1.8371x over previous
#include <cuda_runtime.h>
#include <cuda_bf16.h>
#include <cuda_fp16.h>
#include <cstdint>

// Problem constants
#define Bsz 2
#define Sl  2048
#define Dm  768
#define Iw  1536
#define Nst 16
#define Rr  48
#define Ms  (Bsz * Sl)          // 4096 rows
#define TWO_I (2 * Iw)          // 3072

// ---------------------------------------------------------------------------
// Scratch (device globals)
// ---------------------------------------------------------------------------
__device__ float g_proj[(size_t)Ms * TWO_I];
__device__ float g_h   [(size_t)Ms * Iw];
__device__ float g_ssm [(size_t)Ms * (Rr + 2 * Nst)];
__device__ float g_dt  [(size_t)Ms * Iw];

__device__ __half g_x16[(size_t)Ms * Dm];
__device__ __half g_w1 [(size_t)TWO_I * Dm];
__device__ __half g_y16[(size_t)Ms * Iw];
__device__ __half g_w2 [(size_t)Dm * Iw];

// ---------------------------------------------------------------------------
// Helpers
// ---------------------------------------------------------------------------
__device__ __forceinline__ uint32_t smem_u32(const void* p) {
    uint32_t a;
    asm("{ .reg .u64 t; cvta.to.shared.u64 t, %1; cvt.u32.u64 %0, t; }" : "=r"(a) : "l"(p));
    return a;
}
__device__ __forceinline__ void cp16(uint32_t saddr, const void* gsrc) {
    asm volatile("cp.async.cg.shared.global [%0], [%1], 16;" :: "r"(saddr), "l"(gsrc));
}
#define CP_COMMIT() asm volatile("cp.async.commit_group;" ::: "memory")
#define CP_WAIT(n)  asm volatile("cp.async.wait_group %0;" :: "n"(n) : "memory")

__device__ __forceinline__ void ldm_x4(uint32_t* r, uint32_t addr) {
    asm volatile("ldmatrix.sync.aligned.m8n8.x4.shared.b16 {%0,%1,%2,%3}, [%4];"
                 : "=r"(r[0]), "=r"(r[1]), "=r"(r[2]), "=r"(r[3]) : "r"(addr));
}
__device__ __forceinline__ void ldm_x2(uint32_t* r, uint32_t addr) {
    asm volatile("ldmatrix.sync.aligned.m8n8.x2.shared.b16 {%0,%1}, [%2];"
                 : "=r"(r[0]), "=r"(r[1]) : "r"(addr));
}
__device__ __forceinline__ void mma16816(float* c, const uint32_t* a, const uint32_t* b) {
    asm volatile("mma.sync.aligned.m16n8k16.row.col.f32.f16.f16.f32 "
                 "{%0,%1,%2,%3}, {%4,%5,%6,%7}, {%8,%9}, {%0,%1,%2,%3};"
                 : "+f"(c[0]), "+f"(c[1]), "+f"(c[2]), "+f"(c[3])
                 : "r"(a[0]), "r"(a[1]), "r"(a[2]), "r"(a[3]), "r"(b[0]), "r"(b[1]));
}

// ---------------------------------------------------------------------------
// HMMA fp16 GEMM (single pass): C[M,N] = A16[M,K] @ W16[N,K]^T
// 128x128 CTA tile, BK=32, 256 threads, 2-stage cp.async, 2 CTAs/SM (no spill:
// live set ~90 regs under the 128 cap).
// ---------------------------------------------------------------------------
#define STRD 40
#define TILE_B (128 * STRD * 2)            // 10240 B per matrix tile
#define STAGE_B (2 * TILE_B)               // A, W            (20480)
#define SMEM_B (2 * STAGE_B)               // 40960

__global__ __launch_bounds__(256, 2)
void hmma_f16(const __half* __restrict__ A16, const __half* __restrict__ W16,
              float* __restrict__ C, int M, int N, int K)
{
    extern __shared__ __align__(16) char smem[];
    const uint32_t sb = smem_u32(smem);
    const int tid = threadIdx.x;
    const int wid = tid >> 5, lane = tid & 31;
    const int warp_m = wid >> 2, warp_n = wid & 3;
    const int bm = blockIdx.y * 128, bn = blockIdx.x * 128;

    // per stage: 2 mats x 128 rows x 4 16B-chunks = 1024 slots / 256 thr = 4
    auto load_stage = [&](int st, int k0) {
#pragma unroll
        for (int l = 0; l < 4; l++) {
            int v = tid + l * 256;
            int mat = v >> 9;
            int rem = v & 511;
            int row = rem >> 2;
            int c16 = rem & 3;
            const __half* src = (mat == 0)
                ? A16 + (size_t)(bm + row) * K + k0 + c16 * 8
                : W16 + (size_t)(bn + row) * K + k0 + c16 * 8;
            uint32_t dst = sb + st * STAGE_B + mat * TILE_B + (row * STRD + c16 * 8) * 2;
            cp16(dst, src);
        }
        CP_COMMIT();
    };

    float acc[4][4][4];
#pragma unroll
    for (int i = 0; i < 4; i++)
#pragma unroll
        for (int j = 0; j < 4; j++)
#pragma unroll
            for (int k = 0; k < 4; k++) acc[i][j][k] = 0.f;

    const int nch = K >> 5;
    load_stage(0, 0);

    const int a_r = warp_m * 64 + (lane & 15);
    const int a_k = (lane >> 4) * 8;
    const int b_r = warp_n * 32 + (lane & 7);
    const int b_k = ((lane >> 3) & 1) * 8;

    for (int ch = 0; ch < nch; ch++) {
        const int st = ch & 1;
        if (ch + 1 < nch) load_stage(st ^ 1, (ch + 1) << 5);
        if (ch + 1 < nch) { CP_WAIT(1); } else { CP_WAIT(0); }
        __syncthreads();

        const uint32_t aB = sb + st * STAGE_B;
        const uint32_t wB = aB + TILE_B;

#pragma unroll
        for (int kk = 0; kk < 2; kk++) {
            uint32_t a[4][4], b[4][2];
#pragma unroll
            for (int mt = 0; mt < 4; mt++)
                ldm_x4(a[mt], aB + ((a_r + mt * 16) * STRD + a_k + kk * 16) * 2);
#pragma unroll
            for (int nt = 0; nt < 4; nt++)
                ldm_x2(b[nt], wB + ((b_r + nt * 8) * STRD + b_k + kk * 16) * 2);
#pragma unroll
            for (int mt = 0; mt < 4; mt++)
#pragma unroll
                for (int nt = 0; nt < 4; nt++)
                    mma16816(acc[mt][nt], a[mt], b[nt]);
        }
        __syncthreads();
    }

    const int er = bm + warp_m * 64 + (lane >> 2);
    const int ec = bn + warp_n * 32 + (lane & 3) * 2;
#pragma unroll
    for (int mt = 0; mt < 4; mt++)
#pragma unroll
        for (int nt = 0; nt < 4; nt++) {
            int r = er + mt * 16;
            int c = ec + nt * 8;
            *(float2*)&C[(size_t)r * N + c]       = make_float2(acc[mt][nt][0], acc[mt][nt][1]);
            *(float2*)&C[(size_t)(r + 8) * N + c] = make_float2(acc[mt][nt][2], acc[mt][nt][3]);
        }
}

// ---------------------------------------------------------------------------
// fp32 -> fp16 convert
// ---------------------------------------------------------------------------
__global__ __launch_bounds__(256)
void conv_f16(const float* __restrict__ in, __half* __restrict__ out, int n4)
{
    int i = blockIdx.x * 256 + threadIdx.x;
    if (i >= n4) return;
    float4 v = ((const float4*)in)[i];
    __half2* op = (__half2*)(out + (size_t)i * 4);
    op[0] = __floats2half2_rn(v.x, v.y);
    op[1] = __floats2half2_rn(v.z, v.w);
}

// ---------------------------------------------------------------------------
// fp32 tiled SGEMM (small GEMMs)
// ---------------------------------------------------------------------------
template<int BM, int BN, int BK, int TM, int TN, int EPI>
__global__ __launch_bounds__(256)
void sgemm_nt(const float* __restrict__ A, const float* __restrict__ W,
              float* __restrict__ C, int M, int N, int K, int lda,
              const float* __restrict__ bias,
              const float* __restrict__ lastscale)
{
    constexpr int NT = (BM / TM) * (BN / TN);
    static_assert(NT == 256, "need 256 threads");
    constexpr int LA = (BM * BK) / (4 * NT);
    constexpr int LB = (BN * BK) / (4 * NT);

    __shared__ __align__(16) float As[BK][BM];
    __shared__ __align__(16) float Bs[BK][BN];

    const int tid = threadIdx.x;
    const int bm = blockIdx.y * BM;
    const int bn = blockIdx.x * BN;
    const int tx = tid % (BN / TN);
    const int ty = tid / (BN / TN);

    float acc[TM][TN];
#pragma unroll
    for (int a = 0; a < TM; a++)
#pragma unroll
        for (int b = 0; b < TN; b++) acc[a][b] = 0.f;

    for (int k0 = 0; k0 < K; k0 += BK) {
#pragma unroll
        for (int l = 0; l < LA; l++) {
            int v = tid + l * NT;
            int r = v / (BK / 4);
            int kq = (v % (BK / 4)) * 4;
            int grow = bm + r;
            float4 av = make_float4(0.f, 0.f, 0.f, 0.f);
            if (grow < M)
                av = *(const float4*)(A + (size_t)grow * lda + k0 + kq);
            As[kq + 0][r] = av.x; As[kq + 1][r] = av.y;
            As[kq + 2][r] = av.z; As[kq + 3][r] = av.w;
        }
#pragma unroll
        for (int l = 0; l < LB; l++) {
            int v = tid + l * NT;
            int r = v / (BK / 4);
            int kq = (v % (BK / 4)) * 4;
            int gcol = bn + r;
            float4 wv = make_float4(0.f, 0.f, 0.f, 0.f);
            if (gcol < N)
                wv = *(const float4*)(W + (size_t)gcol * K + k0 + kq);
            Bs[kq + 0][r] = wv.x; Bs[kq + 1][r] = wv.y;
            Bs[kq + 2][r] = wv.z; Bs[kq + 3][r] = wv.w;
        }
        __syncthreads();

#pragma unroll
        for (int k = 0; k < BK; k++) {
            float ra[TM], rb[TN];
#pragma unroll
            for (int u = 0; u < TM / 4; u++)
                *(float4*)&ra[4 * u] = *(const float4*)&As[k][ty * TM + 4 * u];
#pragma unroll
            for (int u = 0; u < TN / 4; u++)
                *(float4*)&rb[4 * u] = *(const float4*)&Bs[k][tx * TN + 4 * u];
#pragma unroll
            for (int a = 0; a < TM; a++)
#pragma unroll
                for (int b = 0; b < TN; b++)
                    acc[a][b] = fmaf(ra[a], rb[b], acc[a][b]);
        }
        __syncthreads();
    }

#pragma unroll
    for (int a = 0; a < TM; a++) {
        int m = bm + ty * TM + a;
        if (m >= M) continue;
        bool last = ((m % Sl) == (Sl - 1));
#pragma unroll
        for (int b = 0; b < TN; b++) {
            int n = bn + tx * TN + b;
            if (n >= N) continue;
            float v = acc[a][b];
            if (EPI == 1) {
                v += bias[n];
                v = (v > 20.f) ? v : log1pf(__expf(v));
                if (last) v *= lastscale[n];
            }
            C[(size_t)m * N + n] = v;
        }
    }
}

// ---------------------------------------------------------------------------
// Causal depthwise conv1d (K=4) + bias + SiLU — rolling-window, 16 s per block
// ---------------------------------------------------------------------------
__global__ __launch_bounds__(256)
void conv_silu2(const float* __restrict__ proj,
                const float* __restrict__ cw,
                const float* __restrict__ cb,
                float* __restrict__ h)
{
    const int blk = blockIdx.x;                 // Bsz * (Sl/16)
    const int b = blk / (Sl / 16);
    const int st = (blk % (Sl / 16)) * 16;

#pragma unroll 1
    for (int ic = 0; ic < Iw / 256; ic++) {
        const int i = ic * 256 + threadIdx.x;
        float4 w = *(const float4*)(cw + (size_t)i * 4);
        const float bia = cb[i];
        const float* base = proj + ((size_t)b * Sl + st) * TWO_I + i;
        float* outp = h + ((size_t)b * Sl + st) * Iw + i;

        float x3, x2, x1;
        if (st > 0) {
            x3 = base[-(size_t)3 * TWO_I];
            x2 = base[-(size_t)2 * TWO_I];
            x1 = base[-(size_t)1 * TWO_I];
        } else {
            x3 = x2 = x1 = 0.f;
        }
#pragma unroll
        for (int s = 0; s < 16; s++) {
            float x0 = base[(size_t)s * TWO_I];
            float acc = fmaf(w.w, x0, fmaf(w.z, x1, fmaf(w.y, x2, fmaf(w.x, x3, bia))));
            float sig = __fdividef(1.f, 1.f + __expf(-acc));
            outp[(size_t)s * Iw] = acc * sig;
            x3 = x2; x2 = x1; x1 = x0;
        }
    }
}

// ---------------------------------------------------------------------------
// Smem-staged selective scan; emits fp16 y directly.
// ---------------------------------------------------------------------------
#define SCT 64
#define NCH (Sl / SCT)

__global__ __launch_bounds__(256)
void scan_kernel2(const float* __restrict__ dt,
                  const float* __restrict__ h,
                  const float* __restrict__ ssm,
                  const float* __restrict__ proj,
                  const float* __restrict__ A_log,
                  const float* __restrict__ Dv,
                  const float* __restrict__ fg,
                  __half* __restrict__ y16)
{
    __shared__ __align__(16) float s_dt[2][SCT][16];
    __shared__ __align__(16) float s_h [2][SCT][16];
    __shared__ __align__(16) float s_g [2][SCT][16];
    __shared__ __align__(16) float s_B [2][SCT][16];
    __shared__ __align__(16) float s_C [2][SCT][16];
    __shared__ __align__(16) float s_y [SCT][16];
    __shared__ float s_D[16];

    const int tid = threadIdx.x;
    const int blk = blockIdx.x;
    const int b = blk / (Iw / 16);
    const int i0 = (blk % (Iw / 16)) * 16;

    const int ci = tid >> 4;
    const int ln = tid & 15;

    if (tid < 16) s_D[tid] = Dv[i0 + tid];

    const float An = -__expf(A_log[(size_t)(i0 + ci) * Nst + ln]);
    float state = 0.f;

    const size_t row0 = (size_t)b * Sl;
    const int lr = tid >> 2, lc = (tid & 3) * 4;

    const uint32_t a_dt = smem_u32(&s_dt[0][0][0]);
    const uint32_t a_h  = smem_u32(&s_h [0][0][0]);
    const uint32_t a_g  = smem_u32(&s_g [0][0][0]);
    const uint32_t a_B  = smem_u32(&s_B [0][0][0]);
    const uint32_t a_C  = smem_u32(&s_C [0][0][0]);
    const uint32_t stoff = SCT * 16 * 4;
    const uint32_t loff = (lr * 16 + lc) * 4;

    auto issue = [&](int st, int s0) {
        size_t r = row0 + s0 + lr;
        cp16(a_dt + st * stoff + loff, dt   + r * Iw + i0 + lc);
        cp16(a_h  + st * stoff + loff, h    + r * Iw + i0 + lc);
        cp16(a_g  + st * stoff + loff, proj + r * TWO_I + Iw + i0 + lc);
        cp16(a_B  + st * stoff + loff, ssm  + r * (Rr + 2 * Nst) + Rr + lc);
        cp16(a_C  + st * stoff + loff, ssm  + r * (Rr + 2 * Nst) + Rr + Nst + lc);
        CP_COMMIT();
    };

    issue(0, 0);

    for (int ch = 0; ch < NCH; ch++) {
        const int st = ch & 1;
        const int s0 = ch * SCT;
        if (ch + 1 < NCH) { issue(st ^ 1, s0 + SCT); CP_WAIT(1); }
        else              { CP_WAIT(0); }
        __syncthreads();

#pragma unroll 4
        for (int s = 0; s < SCT; s++) {
            float dtv = s_dt[st][s][ci];
            float hv  = s_h [st][s][ci];
            float dA  = __expf(An * dtv);
            state = fmaf(dA, state, dtv * s_B[st][s][ln] * hv);
            float part = state * s_C[st][s][ln];
            part += __shfl_xor_sync(0xffffffffu, part, 8);
            part += __shfl_xor_sync(0xffffffffu, part, 4);
            part += __shfl_xor_sync(0xffffffffu, part, 2);
            part += __shfl_xor_sync(0xffffffffu, part, 1);
            if (ln == 0) s_y[s][ci] = part;
        }
        __syncthreads();

#pragma unroll
        for (int k = 0; k < 4; k++) {
            int idx = tid + k * 256;
            int r = idx >> 4, c = idx & 15;
            float hv = s_h[st][r][c];
            float g  = s_g[st][r][c];
            float sg = g * __fdividef(1.f, 1.f + __expf(-g));
            float val = (s_y[r][c] + hv * s_D[c]) * sg;
            if (s0 + r == Sl - 1) val *= fg[i0 + c];
            y16[(row0 + s0 + r) * Iw + i0 + c] = __float2half_rn(val);
        }
        __syncthreads();
    }
}

// ---------------------------------------------------------------------------
// Launch
// ---------------------------------------------------------------------------
extern "C" void kernel_launch(void* const* d_in, const int* in_sizes, int n_in,
                              void* d_out, int out_size)
{
    const float* x          = (const float*)d_in[0];
    const float* in_proj_w  = (const float*)d_in[1];
    const float* conv_w     = (const float*)d_in[2];
    const float* conv_b     = (const float*)d_in[3];
    const float* x_proj_w   = (const float*)d_in[4];
    const float* dt_proj_w  = (const float*)d_in[5];
    const float* dt_proj_b  = (const float*)d_in[6];
    const float* A_log      = (const float*)d_in[7];
    const float* Dv         = (const float*)d_in[8];
    const float* out_proj_w = (const float*)d_in[9];
    const float* alpha      = (const float*)d_in[10];
    const float* fg         = (const float*)d_in[11];
    float* out = (float*)d_out;

    float *proj, *h, *ssm, *dt;
    cudaGetSymbolAddress((void**)&proj, g_proj);
    cudaGetSymbolAddress((void**)&h,    g_h);
    cudaGetSymbolAddress((void**)&ssm,  g_ssm);
    cudaGetSymbolAddress((void**)&dt,   g_dt);

    __half *x16, *w1, *y16, *w2;
    cudaGetSymbolAddress((void**)&x16, g_x16);
    cudaGetSymbolAddress((void**)&w1,  g_w1);
    cudaGetSymbolAddress((void**)&y16, g_y16);
    cudaGetSymbolAddress((void**)&w2,  g_w2);

    cudaFuncSetAttribute(hmma_f16, cudaFuncAttributeMaxDynamicSharedMemorySize, SMEM_B);

    // 0-2) fp16 conversions
    {
        int n4 = (Ms * Dm) / 4;
        conv_f16<<<(n4 + 255) / 256, 256>>>(x, x16, n4);
        n4 = (TWO_I * Dm) / 4;
        conv_f16<<<(n4 + 255) / 256, 256>>>(in_proj_w, w1, n4);
        n4 = (Dm * Iw) / 4;
        conv_f16<<<(n4 + 255) / 256, 256>>>(out_proj_w, w2, n4);
    }

    // 3) in_proj (HMMA fp16): proj[4096,3072] = x16 @ w1^T
    hmma_f16<<<dim3(TWO_I / 128, Ms / 128), 256, SMEM_B>>>(
        x16, w1, proj, Ms, TWO_I, Dm);

    // 4) conv + SiLU (rolling window)
    conv_silu2<<<Bsz * (Sl / 16), 256>>>(proj, conv_w, conv_b, h);

    // 5) x_proj (fp32)
    sgemm_nt<64,64,16,4,4,0><<<dim3(2, Ms/64), 256>>>(
        h, x_proj_w, ssm, Ms, Rr + 2*Nst, Iw, Iw, nullptr, nullptr);

    // 6) dt_proj + softplus + alpha
    sgemm_nt<64,64,16,4,4,1><<<dim3(Iw/64, Ms/64), 256>>>(
        ssm, dt_proj_w, dt, Ms, Iw, Rr, Rr + 2*Nst, dt_proj_b, alpha);

    // 7) scan (emits fp16 y)
    scan_kernel2<<<(Bsz * Iw) / 16, 256>>>(dt, h, ssm, proj, A_log, Dv, fg, y16);

    // 8) out_proj (HMMA fp16): out[4096,768] = y16 @ w2^T
    hmma_f16<<<dim3(Dm / 128, Ms / 128), 256, SMEM_B>>>(
        y16, w2, out, Ms, Dm, Iw);
}

// round 8
// speedup vs baseline: 2.0475x; 1.1145x over previous
#include <cuda_runtime.h>
#include <cuda_bf16.h>
#include <cuda_fp16.h>
#include <cstdint>

// Problem constants
#define Bsz 2
#define Sl  2048
#define Dm  768
#define Iw  1536
#define Nst 16
#define Rr  48
#define Ms  (Bsz * Sl)          // 4096 rows
#define TWO_I (2 * Iw)          // 3072

// ---------------------------------------------------------------------------
// Scratch (device globals)
// ---------------------------------------------------------------------------
__device__ float g_proj[(size_t)Ms * TWO_I];
__device__ float g_h   [(size_t)Ms * Iw];
__device__ float g_ssm [(size_t)Ms * (Rr + 2 * Nst)];
__device__ float g_dt  [(size_t)Ms * Iw];

__device__ __half g_x16[(size_t)Ms * Dm];
__device__ __half g_w1 [(size_t)TWO_I * Dm];
__device__ __half g_y16[(size_t)Ms * Iw];
__device__ __half g_w2 [(size_t)Dm * Iw];

// ---------------------------------------------------------------------------
// Helpers
// ---------------------------------------------------------------------------
__device__ __forceinline__ uint32_t smem_u32(const void* p) {
    uint32_t a;
    asm("{ .reg .u64 t; cvta.to.shared.u64 t, %1; cvt.u32.u64 %0, t; }" : "=r"(a) : "l"(p));
    return a;
}
__device__ __forceinline__ void cp16(uint32_t saddr, const void* gsrc) {
    asm volatile("cp.async.cg.shared.global [%0], [%1], 16;" :: "r"(saddr), "l"(gsrc));
}
#define CP_COMMIT() asm volatile("cp.async.commit_group;" ::: "memory")
#define CP_WAIT(n)  asm volatile("cp.async.wait_group %0;" :: "n"(n) : "memory")

__device__ __forceinline__ void ldm_x4(uint32_t* r, uint32_t addr) {
    asm volatile("ldmatrix.sync.aligned.m8n8.x4.shared.b16 {%0,%1,%2,%3}, [%4];"
                 : "=r"(r[0]), "=r"(r[1]), "=r"(r[2]), "=r"(r[3]) : "r"(addr));
}
__device__ __forceinline__ void ldm_x2(uint32_t* r, uint32_t addr) {
    asm volatile("ldmatrix.sync.aligned.m8n8.x2.shared.b16 {%0,%1}, [%2];"
                 : "=r"(r[0]), "=r"(r[1]) : "r"(addr));
}
__device__ __forceinline__ void mma16816(float* c, const uint32_t* a, const uint32_t* b) {
    asm volatile("mma.sync.aligned.m16n8k16.row.col.f32.f16.f16.f32 "
                 "{%0,%1,%2,%3}, {%4,%5,%6,%7}, {%8,%9}, {%0,%1,%2,%3};"
                 : "+f"(c[0]), "+f"(c[1]), "+f"(c[2]), "+f"(c[3])
                 : "r"(a[0]), "r"(a[1]), "r"(a[2]), "r"(a[3]), "r"(b[0]), "r"(b[1]));
}

// ---------------------------------------------------------------------------
// HMMA fp16 GEMM (single pass): C[M,N] = A16[M,K] @ W16[N,K]^T
// Templated on BN (128 or 64). 3-stage cp.async pipeline, 256 threads,
// 2 CTAs/SM.
// ---------------------------------------------------------------------------
#define STRD 40
#define A_TILE_B (128 * STRD * 2)           // 10240

template<int BN>
__global__ __launch_bounds__(256, 2)
void hmma_f16(const __half* __restrict__ A16, const __half* __restrict__ W16,
              float* __restrict__ C, int M, int N, int K)
{
    constexpr int NWN = BN / 32;            // warps along n
    constexpr int NWM = 8 / NWN;            // warps along m
    constexpr int MT  = 128 / (NWM * 16);   // 16-row m-tiles per warp
    constexpr int W_TILE_B = BN * STRD * 2;
    constexpr int STAGE = A_TILE_B + W_TILE_B;
    constexpr int NSLOT = (128 + BN) * 4;   // 16B slots per stage

    extern __shared__ __align__(16) char smem[];
    const uint32_t sb = smem_u32(smem);
    const int tid = threadIdx.x;
    const int wid = tid >> 5, lane = tid & 31;
    const int warp_m = wid / NWN, warp_n = wid % NWN;
    const int bm = blockIdx.y * 128, bn = blockIdx.x * BN;

    auto load_stage = [&](int st, int k0) {
#pragma unroll
        for (int v = tid; v < NSLOT; v += 256) {
            int row, c16;
            const __half* src;
            uint32_t base;
            if (v < 512) {
                row = v >> 2; c16 = v & 3;
                src = A16 + (size_t)(bm + row) * K + k0 + c16 * 8;
                base = 0;
            } else {
                int u = v - 512;
                row = u >> 2; c16 = u & 3;
                src = W16 + (size_t)(bn + row) * K + k0 + c16 * 8;
                base = A_TILE_B;
            }
            cp16(sb + st * STAGE + base + (row * STRD + c16 * 8) * 2, src);
        }
        CP_COMMIT();
    };

    float acc[MT][4][4];
#pragma unroll
    for (int i = 0; i < MT; i++)
#pragma unroll
        for (int j = 0; j < 4; j++)
#pragma unroll
            for (int k = 0; k < 4; k++) acc[i][j][k] = 0.f;

    const int nch = K >> 5;
    load_stage(0, 0);
    if (nch > 1) load_stage(1, 32);

    const int a_r = warp_m * (MT * 16) + (lane & 15);
    const int a_k = (lane >> 4) * 8;
    const int b_r = warp_n * 32 + (lane & 7);
    const int b_k = ((lane >> 3) & 1) * 8;

    for (int ch = 0; ch < nch; ch++) {
        const int st = ch % 3;
        if (ch == nch - 1) { CP_WAIT(0); } else { CP_WAIT(1); }
        __syncthreads();
        if (ch + 2 < nch) load_stage((ch + 2) % 3, (ch + 2) << 5);

        const uint32_t aB = sb + st * STAGE;
        const uint32_t wB = aB + A_TILE_B;

#pragma unroll
        for (int kk = 0; kk < 2; kk++) {
            uint32_t a[MT][4], b[4][2];
#pragma unroll
            for (int mt = 0; mt < MT; mt++)
                ldm_x4(a[mt], aB + ((a_r + mt * 16) * STRD + a_k + kk * 16) * 2);
#pragma unroll
            for (int nt = 0; nt < 4; nt++)
                ldm_x2(b[nt], wB + ((b_r + nt * 8) * STRD + b_k + kk * 16) * 2);
#pragma unroll
            for (int mt = 0; mt < MT; mt++)
#pragma unroll
                for (int nt = 0; nt < 4; nt++)
                    mma16816(acc[mt][nt], a[mt], b[nt]);
        }
        __syncthreads();
    }

    const int er = bm + warp_m * (MT * 16) + (lane >> 2);
    const int ec = bn + warp_n * 32 + (lane & 3) * 2;
#pragma unroll
    for (int mt = 0; mt < MT; mt++)
#pragma unroll
        for (int nt = 0; nt < 4; nt++) {
            int r = er + mt * 16;
            int c = ec + nt * 8;
            *(float2*)&C[(size_t)r * N + c]       = make_float2(acc[mt][nt][0], acc[mt][nt][1]);
            *(float2*)&C[(size_t)(r + 8) * N + c] = make_float2(acc[mt][nt][2], acc[mt][nt][3]);
        }
}

// ---------------------------------------------------------------------------
// fp32 -> fp16 convert
// ---------------------------------------------------------------------------
__global__ __launch_bounds__(256)
void conv_f16(const float* __restrict__ in, __half* __restrict__ out, int n4)
{
    int i = blockIdx.x * 256 + threadIdx.x;
    if (i >= n4) return;
    float4 v = ((const float4*)in)[i];
    __half2* op = (__half2*)(out + (size_t)i * 4);
    op[0] = __floats2half2_rn(v.x, v.y);
    op[1] = __floats2half2_rn(v.z, v.w);
}

// ---------------------------------------------------------------------------
// fp32 tiled SGEMM (small GEMMs). EPI 1: fast softplus + alpha on last step.
// ---------------------------------------------------------------------------
template<int BM, int BN, int BK, int TM, int TN, int EPI>
__global__ __launch_bounds__(256)
void sgemm_nt(const float* __restrict__ A, const float* __restrict__ W,
              float* __restrict__ C, int M, int N, int K, int lda,
              const float* __restrict__ bias,
              const float* __restrict__ lastscale)
{
    constexpr int NT = (BM / TM) * (BN / TN);
    static_assert(NT == 256, "need 256 threads");
    constexpr int LA = (BM * BK) / (4 * NT);
    constexpr int LB = (BN * BK) / (4 * NT);

    __shared__ __align__(16) float As[BK][BM];
    __shared__ __align__(16) float Bs[BK][BN];

    const int tid = threadIdx.x;
    const int bm = blockIdx.y * BM;
    const int bn = blockIdx.x * BN;
    const int tx = tid % (BN / TN);
    const int ty = tid / (BN / TN);

    float acc[TM][TN];
#pragma unroll
    for (int a = 0; a < TM; a++)
#pragma unroll
        for (int b = 0; b < TN; b++) acc[a][b] = 0.f;

    for (int k0 = 0; k0 < K; k0 += BK) {
#pragma unroll
        for (int l = 0; l < LA; l++) {
            int v = tid + l * NT;
            int r = v / (BK / 4);
            int kq = (v % (BK / 4)) * 4;
            int grow = bm + r;
            float4 av = make_float4(0.f, 0.f, 0.f, 0.f);
            if (grow < M)
                av = *(const float4*)(A + (size_t)grow * lda + k0 + kq);
            As[kq + 0][r] = av.x; As[kq + 1][r] = av.y;
            As[kq + 2][r] = av.z; As[kq + 3][r] = av.w;
        }
#pragma unroll
        for (int l = 0; l < LB; l++) {
            int v = tid + l * NT;
            int r = v / (BK / 4);
            int kq = (v % (BK / 4)) * 4;
            int gcol = bn + r;
            float4 wv = make_float4(0.f, 0.f, 0.f, 0.f);
            if (gcol < N)
                wv = *(const float4*)(W + (size_t)gcol * K + k0 + kq);
            Bs[kq + 0][r] = wv.x; Bs[kq + 1][r] = wv.y;
            Bs[kq + 2][r] = wv.z; Bs[kq + 3][r] = wv.w;
        }
        __syncthreads();

#pragma unroll
        for (int k = 0; k < BK; k++) {
            float ra[TM], rb[TN];
#pragma unroll
            for (int u = 0; u < TM / 4; u++)
                *(float4*)&ra[4 * u] = *(const float4*)&As[k][ty * TM + 4 * u];
#pragma unroll
            for (int u = 0; u < TN / 4; u++)
                *(float4*)&rb[4 * u] = *(const float4*)&Bs[k][tx * TN + 4 * u];
#pragma unroll
            for (int a = 0; a < TM; a++)
#pragma unroll
                for (int b = 0; b < TN; b++)
                    acc[a][b] = fmaf(ra[a], rb[b], acc[a][b]);
        }
        __syncthreads();
    }

#pragma unroll
    for (int a = 0; a < TM; a++) {
        int m = bm + ty * TM + a;
        if (m >= M) continue;
        bool last = ((m % Sl) == (Sl - 1));
#pragma unroll
        for (int b = 0; b < TN; b++) {
            int n = bn + tx * TN + b;
            if (n >= N) continue;
            float v = acc[a][b];
            if (EPI == 1) {
                v += bias[n];
                v = (v > 15.f) ? v : __logf(1.f + __expf(v));
                if (last) v *= lastscale[n];
            }
            C[(size_t)m * N + n] = v;
        }
    }
}

// ---------------------------------------------------------------------------
// Causal depthwise conv1d (K=4) + bias + SiLU — rolling-window
// ---------------------------------------------------------------------------
__global__ __launch_bounds__(256)
void conv_silu2(const float* __restrict__ proj,
                const float* __restrict__ cw,
                const float* __restrict__ cb,
                float* __restrict__ h)
{
    const int blk = blockIdx.x;                 // Bsz * (Sl/16)
    const int b = blk / (Sl / 16);
    const int st = (blk % (Sl / 16)) * 16;

#pragma unroll 1
    for (int ic = 0; ic < Iw / 256; ic++) {
        const int i = ic * 256 + threadIdx.x;
        float4 w = *(const float4*)(cw + (size_t)i * 4);
        const float bia = cb[i];
        const float* base = proj + ((size_t)b * Sl + st) * TWO_I + i;
        float* outp = h + ((size_t)b * Sl + st) * Iw + i;

        float x3, x2, x1;
        if (st > 0) {
            x3 = base[-(size_t)3 * TWO_I];
            x2 = base[-(size_t)2 * TWO_I];
            x1 = base[-(size_t)1 * TWO_I];
        } else {
            x3 = x2 = x1 = 0.f;
        }
#pragma unroll
        for (int s = 0; s < 16; s++) {
            float x0 = base[(size_t)s * TWO_I];
            float acc = fmaf(w.w, x0, fmaf(w.z, x1, fmaf(w.y, x2, fmaf(w.x, x3, bia))));
            float sig = __fdividef(1.f, 1.f + __expf(-acc));
            outp[(size_t)s * Iw] = acc * sig;
            x3 = x2; x2 = x1; x1 = x0;
        }
    }
}

// ---------------------------------------------------------------------------
// Selective scan v3: 4 states/lane, 8 channels/warp, 64-thread blocks.
// Shfl depth 2, float4 B/C loads, cp.async double-buffered smem staging.
// Emits fp16 y directly (fused D, silu(gate), fg epilogue).
// ---------------------------------------------------------------------------
#define SCT 64
#define NCH (Sl / SCT)

__global__ __launch_bounds__(64)
void scan_kernel3(const float* __restrict__ dt,
                  const float* __restrict__ h,
                  const float* __restrict__ ssm,
                  const float* __restrict__ proj,
                  const float* __restrict__ A_log,
                  const float* __restrict__ Dv,
                  const float* __restrict__ fg,
                  __half* __restrict__ y16)
{
    __shared__ __align__(16) float s_dt[2][SCT][16];
    __shared__ __align__(16) float s_h [2][SCT][16];
    __shared__ __align__(16) float s_g [2][SCT][16];
    __shared__ __align__(16) float s_B [2][SCT][16];
    __shared__ __align__(16) float s_C [2][SCT][16];
    __shared__ __align__(16) float s_y [SCT][16];
    __shared__ float s_D[16];

    const int tid = threadIdx.x;                // 0..63
    const int blk = blockIdx.x;                 // 0..191
    const int b = blk / (Iw / 16);
    const int i0 = (blk % (Iw / 16)) * 16;

    const int wid = tid >> 5;                   // 0..1
    const int lane = tid & 31;
    const int ci = wid * 8 + (lane >> 2);       // channel 0..15
    const int subl = lane & 3;                  // state quad

    if (tid < 16) s_D[tid] = Dv[i0 + tid];

    float An[4];
#pragma unroll
    for (int j = 0; j < 4; j++)
        An[j] = -__expf(A_log[(size_t)(i0 + ci) * Nst + subl * 4 + j]);
    float st4[4] = {0.f, 0.f, 0.f, 0.f};

    const size_t row0 = (size_t)b * Sl;

    const uint32_t a_dt = smem_u32(&s_dt[0][0][0]);
    const uint32_t a_h  = smem_u32(&s_h [0][0][0]);
    const uint32_t a_g  = smem_u32(&s_g [0][0][0]);
    const uint32_t a_B  = smem_u32(&s_B [0][0][0]);
    const uint32_t a_C  = smem_u32(&s_C [0][0][0]);
    const uint32_t stoff = SCT * 16 * 4;

    auto issue = [&](int st, int s0) {
#pragma unroll
        for (int l = 0; l < 4; l++) {
            int v = tid + l * 64;
            int r = v >> 2, c4 = (v & 3) * 4;
            size_t grow = row0 + s0 + r;
            uint32_t off = st * stoff + (r * 16 + c4) * 4;
            cp16(a_dt + off, dt   + grow * Iw + i0 + c4);
            cp16(a_h  + off, h    + grow * Iw + i0 + c4);
            cp16(a_g  + off, proj + grow * TWO_I + Iw + i0 + c4);
            cp16(a_B  + off, ssm  + grow * (Rr + 2 * Nst) + Rr + c4);
            cp16(a_C  + off, ssm  + grow * (Rr + 2 * Nst) + Rr + Nst + c4);
        }
        CP_COMMIT();
    };

    issue(0, 0);

    for (int ch = 0; ch < NCH; ch++) {
        const int st = ch & 1;
        const int s0 = ch * SCT;
        if (ch + 1 < NCH) { issue(st ^ 1, s0 + SCT); CP_WAIT(1); }
        else              { CP_WAIT(0); }
        __syncthreads();

#pragma unroll 4
        for (int s = 0; s < SCT; s++) {
            float dtv = s_dt[st][s][ci];
            float hv  = s_h [st][s][ci];
            float4 Bv = *(const float4*)&s_B[st][s][subl * 4];
            float4 Cv = *(const float4*)&s_C[st][s][subl * 4];
            float dth = dtv * hv;
            st4[0] = fmaf(__expf(An[0] * dtv), st4[0], dth * Bv.x);
            st4[1] = fmaf(__expf(An[1] * dtv), st4[1], dth * Bv.y);
            st4[2] = fmaf(__expf(An[2] * dtv), st4[2], dth * Bv.z);
            st4[3] = fmaf(__expf(An[3] * dtv), st4[3], dth * Bv.w);
            float part = st4[0] * Cv.x + st4[1] * Cv.y + st4[2] * Cv.z + st4[3] * Cv.w;
            part += __shfl_xor_sync(0xffffffffu, part, 2);
            part += __shfl_xor_sync(0xffffffffu, part, 1);
            if (subl == 0) s_y[s][ci] = part;
        }
        __syncthreads();

        // parallel epilogue + fp16 writeout
#pragma unroll
        for (int k = 0; k < 16; k++) {
            int idx = tid + k * 64;
            int r = idx >> 4, c = idx & 15;
            float hv = s_h[st][r][c];
            float g  = s_g[st][r][c];
            float sg = g * __fdividef(1.f, 1.f + __expf(-g));
            float val = (s_y[r][c] + hv * s_D[c]) * sg;
            if (s0 + r == Sl - 1) val *= fg[i0 + c];
            y16[(row0 + s0 + r) * Iw + i0 + c] = __float2half_rn(val);
        }
        __syncthreads();
    }
}

// ---------------------------------------------------------------------------
// Launch
// ---------------------------------------------------------------------------
extern "C" void kernel_launch(void* const* d_in, const int* in_sizes, int n_in,
                              void* d_out, int out_size)
{
    const float* x          = (const float*)d_in[0];
    const float* in_proj_w  = (const float*)d_in[1];
    const float* conv_w     = (const float*)d_in[2];
    const float* conv_b     = (const float*)d_in[3];
    const float* x_proj_w   = (const float*)d_in[4];
    const float* dt_proj_w  = (const float*)d_in[5];
    const float* dt_proj_b  = (const float*)d_in[6];
    const float* A_log      = (const float*)d_in[7];
    const float* Dv         = (const float*)d_in[8];
    const float* out_proj_w = (const float*)d_in[9];
    const float* alpha      = (const float*)d_in[10];
    const float* fg         = (const float*)d_in[11];
    float* out = (float*)d_out;

    float *proj, *h, *ssm, *dt;
    cudaGetSymbolAddress((void**)&proj, g_proj);
    cudaGetSymbolAddress((void**)&h,    g_h);
    cudaGetSymbolAddress((void**)&ssm,  g_ssm);
    cudaGetSymbolAddress((void**)&dt,   g_dt);

    __half *x16, *w1, *y16, *w2;
    cudaGetSymbolAddress((void**)&x16, g_x16);
    cudaGetSymbolAddress((void**)&w1,  g_w1);
    cudaGetSymbolAddress((void**)&y16, g_y16);
    cudaGetSymbolAddress((void**)&w2,  g_w2);

    constexpr int SMEM128 = 3 * (A_TILE_B + 128 * STRD * 2);   // 61440
    constexpr int SMEM64  = 3 * (A_TILE_B + 64 * STRD * 2);    // 46080
    cudaFuncSetAttribute(hmma_f16<128>, cudaFuncAttributeMaxDynamicSharedMemorySize, SMEM128);
    cudaFuncSetAttribute(hmma_f16<64>,  cudaFuncAttributeMaxDynamicSharedMemorySize, SMEM64);

    // 0-2) fp16 conversions
    {
        int n4 = (Ms * Dm) / 4;
        conv_f16<<<(n4 + 255) / 256, 256>>>(x, x16, n4);
        n4 = (TWO_I * Dm) / 4;
        conv_f16<<<(n4 + 255) / 256, 256>>>(in_proj_w, w1, n4);
        n4 = (Dm * Iw) / 4;
        conv_f16<<<(n4 + 255) / 256, 256>>>(out_proj_w, w2, n4);
    }

    // 3) in_proj (HMMA fp16): proj[4096,3072] = x16 @ w1^T
    hmma_f16<128><<<dim3(TWO_I / 128, Ms / 128), 256, SMEM128>>>(
        x16, w1, proj, Ms, TWO_I, Dm);

    // 4) conv + SiLU (rolling window)
    conv_silu2<<<Bsz * (Sl / 16), 256>>>(proj, conv_w, conv_b, h);

    // 5) x_proj (fp32)
    sgemm_nt<64,64,16,4,4,0><<<dim3(2, Ms/64), 256>>>(
        h, x_proj_w, ssm, Ms, Rr + 2*Nst, Iw, Iw, nullptr, nullptr);

    // 6) dt_proj + fast softplus + alpha
    sgemm_nt<64,64,16,4,4,1><<<dim3(Iw/64, Ms/64), 256>>>(
        ssm, dt_proj_w, dt, Ms, Iw, Rr, Rr + 2*Nst, dt_proj_b, alpha);

    // 7) scan v3 (emits fp16 y)
    scan_kernel3<<<(Bsz * Iw) / 16, 64>>>(dt, h, ssm, proj, A_log, Dv, fg, y16);

    // 8) out_proj (HMMA fp16, BN=64): out[4096,768] = y16 @ w2^T
    hmma_f16<64><<<dim3(Dm / 64, Ms / 128), 256, SMEM64>>>(
        y16, w2, out, Ms, Dm, Iw);
}

// round 9
// speedup vs baseline: 2.3482x; 1.1469x over previous
#include <cuda_runtime.h>
#include <cuda_bf16.h>
#include <cuda_fp16.h>
#include <cstdint>

// Problem constants
#define Bsz 2
#define Sl  2048
#define Dm  768
#define Iw  1536
#define Nst 16
#define Rr  48
#define Ms  (Bsz * Sl)          // 4096 rows
#define TWO_I (2 * Iw)          // 3072

// ---------------------------------------------------------------------------
// Scratch (device globals)
// ---------------------------------------------------------------------------
__device__ float g_proj[(size_t)Ms * TWO_I];
__device__ float g_h   [(size_t)Ms * Iw];
__device__ float g_ssm [(size_t)Ms * (Rr + 2 * Nst)];
__device__ float g_dt  [(size_t)Ms * Iw];

__device__ __half g_x16 [(size_t)Ms * Dm];
__device__ __half g_w1  [(size_t)TWO_I * Dm];
__device__ __half g_h16 [(size_t)Ms * Iw];
__device__ __half g_wx16[(size_t)128 * Iw];     // x_proj_w padded 80->128 rows
__device__ __half g_y16 [(size_t)Ms * Iw];
__device__ __half g_w2  [(size_t)Dm * Iw];

// ---------------------------------------------------------------------------
// Helpers
// ---------------------------------------------------------------------------
__device__ __forceinline__ uint32_t smem_u32(const void* p) {
    uint32_t a;
    asm("{ .reg .u64 t; cvta.to.shared.u64 t, %1; cvt.u32.u64 %0, t; }" : "=r"(a) : "l"(p));
    return a;
}
__device__ __forceinline__ void cp16(uint32_t saddr, const void* gsrc) {
    asm volatile("cp.async.cg.shared.global [%0], [%1], 16;" :: "r"(saddr), "l"(gsrc));
}
#define CP_COMMIT() asm volatile("cp.async.commit_group;" ::: "memory")
#define CP_WAIT(n)  asm volatile("cp.async.wait_group %0;" :: "n"(n) : "memory")

__device__ __forceinline__ void ldm_x4(uint32_t* r, uint32_t addr) {
    asm volatile("ldmatrix.sync.aligned.m8n8.x4.shared.b16 {%0,%1,%2,%3}, [%4];"
                 : "=r"(r[0]), "=r"(r[1]), "=r"(r[2]), "=r"(r[3]) : "r"(addr));
}
__device__ __forceinline__ void ldm_x2(uint32_t* r, uint32_t addr) {
    asm volatile("ldmatrix.sync.aligned.m8n8.x2.shared.b16 {%0,%1}, [%2];"
                 : "=r"(r[0]), "=r"(r[1]) : "r"(addr));
}
__device__ __forceinline__ void mma16816(float* c, const uint32_t* a, const uint32_t* b) {
    asm volatile("mma.sync.aligned.m16n8k16.row.col.f32.f16.f16.f32 "
                 "{%0,%1,%2,%3}, {%4,%5,%6,%7}, {%8,%9}, {%0,%1,%2,%3};"
                 : "+f"(c[0]), "+f"(c[1]), "+f"(c[2]), "+f"(c[3])
                 : "r"(a[0]), "r"(a[1]), "r"(a[2]), "r"(a[3]), "r"(b[0]), "r"(b[1]));
}

// ---------------------------------------------------------------------------
// HMMA fp16 GEMM: C[M, ldC] (cols < Nstore) = A16[M,K] @ W16[.,K]^T
// 128xBN CTA tile, BK=32, 256 threads, 3-stage cp.async, ONE sync per chunk.
// ---------------------------------------------------------------------------
#define STRD 40
#define A_TILE_B (128 * STRD * 2)           // 10240

template<int BN>
__global__ __launch_bounds__(256, 2)
void hmma_f16(const __half* __restrict__ A16, const __half* __restrict__ W16,
              float* __restrict__ C, int M, int K, int ldC, int Nstore)
{
    constexpr int NWN = BN / 32;            // warps along n
    constexpr int NWM = 8 / NWN;            // warps along m
    constexpr int MT  = 128 / (NWM * 16);   // 16-row m-tiles per warp
    constexpr int W_TILE_B = BN * STRD * 2;
    constexpr int STAGE = A_TILE_B + W_TILE_B;
    constexpr int NSLOT = (128 + BN) * 4;   // 16B slots per stage

    extern __shared__ __align__(16) char smem[];
    const uint32_t sb = smem_u32(smem);
    const int tid = threadIdx.x;
    const int wid = tid >> 5, lane = tid & 31;
    const int warp_m = wid / NWN, warp_n = wid % NWN;
    const int bm = blockIdx.y * 128, bn = blockIdx.x * BN;

    auto load_stage = [&](int st, int k0) {
#pragma unroll
        for (int v = tid; v < NSLOT; v += 256) {
            int row, c16;
            const __half* src;
            uint32_t base;
            if (v < 512) {
                row = v >> 2; c16 = v & 3;
                src = A16 + (size_t)(bm + row) * K + k0 + c16 * 8;
                base = 0;
            } else {
                int u = v - 512;
                row = u >> 2; c16 = u & 3;
                src = W16 + (size_t)(bn + row) * K + k0 + c16 * 8;
                base = A_TILE_B;
            }
            cp16(sb + st * STAGE + base + (row * STRD + c16 * 8) * 2, src);
        }
        CP_COMMIT();
    };

    float acc[MT][4][4];
#pragma unroll
    for (int i = 0; i < MT; i++)
#pragma unroll
        for (int j = 0; j < 4; j++)
#pragma unroll
            for (int k = 0; k < 4; k++) acc[i][j][k] = 0.f;

    const int nch = K >> 5;
    load_stage(0, 0);
    if (nch > 1) load_stage(1, 32);

    const int a_r = warp_m * (MT * 16) + (lane & 15);
    const int a_k = (lane >> 4) * 8;
    const int b_r = warp_n * 32 + (lane & 7);
    const int b_k = ((lane >> 3) & 1) * 8;

    for (int ch = 0; ch < nch; ch++) {
        const int st = ch % 3;
        if (ch == nch - 1) { CP_WAIT(0); } else { CP_WAIT(1); }
        __syncthreads();
        // safe: write-stage (ch+2)%3 was last read in iter ch-1, which the
        // barrier above proves complete for all warps.
        if (ch + 2 < nch) load_stage((ch + 2) % 3, (ch + 2) << 5);

        const uint32_t aB = sb + st * STAGE;
        const uint32_t wB = aB + A_TILE_B;

#pragma unroll
        for (int kk = 0; kk < 2; kk++) {
            uint32_t a[MT][4], b[4][2];
#pragma unroll
            for (int mt = 0; mt < MT; mt++)
                ldm_x4(a[mt], aB + ((a_r + mt * 16) * STRD + a_k + kk * 16) * 2);
#pragma unroll
            for (int nt = 0; nt < 4; nt++)
                ldm_x2(b[nt], wB + ((b_r + nt * 8) * STRD + b_k + kk * 16) * 2);
#pragma unroll
            for (int mt = 0; mt < MT; mt++)
#pragma unroll
                for (int nt = 0; nt < 4; nt++)
                    mma16816(acc[mt][nt], a[mt], b[nt]);
        }
    }

    const int er = bm + warp_m * (MT * 16) + (lane >> 2);
    const int ec = bn + warp_n * 32 + (lane & 3) * 2;
#pragma unroll
    for (int mt = 0; mt < MT; mt++)
#pragma unroll
        for (int nt = 0; nt < 4; nt++) {
            int r = er + mt * 16;
            int c = ec + nt * 8;
            if (c < Nstore) {
                *(float2*)&C[(size_t)r * ldC + c]       = make_float2(acc[mt][nt][0], acc[mt][nt][1]);
                *(float2*)&C[(size_t)(r + 8) * ldC + c] = make_float2(acc[mt][nt][2], acc[mt][nt][3]);
            }
        }
}

// ---------------------------------------------------------------------------
// fp32 -> fp16 convert; wx variant zero-pads rows 80..127
// ---------------------------------------------------------------------------
__global__ __launch_bounds__(256)
void conv_f16(const float* __restrict__ in, __half* __restrict__ out, int n4)
{
    int i = blockIdx.x * 256 + threadIdx.x;
    if (i >= n4) return;
    float4 v = ((const float4*)in)[i];
    __half2* op = (__half2*)(out + (size_t)i * 4);
    op[0] = __floats2half2_rn(v.x, v.y);
    op[1] = __floats2half2_rn(v.z, v.w);
}

__global__ __launch_bounds__(256)
void conv_wx(const float* __restrict__ w, __half* __restrict__ out)
{
    int i = blockIdx.x * 256 + threadIdx.x;          // vec4 index over 128*1536
    if (i >= (128 * Iw) / 4) return;
    int row = (i * 4) / Iw;
    __half2* op = (__half2*)(out + (size_t)i * 4);
    if (row < Rr + 2 * Nst) {
        float4 v = ((const float4*)w)[i];
        op[0] = __floats2half2_rn(v.x, v.y);
        op[1] = __floats2half2_rn(v.z, v.w);
    } else {
        op[0] = __half2(__half(0.f), __half(0.f));
        op[1] = __half2(__half(0.f), __half(0.f));
    }
}

// ---------------------------------------------------------------------------
// fp32 tiled SGEMM (dt_proj). EPI 1: fast softplus + alpha on last step.
// ---------------------------------------------------------------------------
template<int BM, int BN, int BK, int TM, int TN, int EPI>
__global__ __launch_bounds__(256)
void sgemm_nt(const float* __restrict__ A, const float* __restrict__ W,
              float* __restrict__ C, int M, int N, int K, int lda,
              const float* __restrict__ bias,
              const float* __restrict__ lastscale)
{
    constexpr int NT = (BM / TM) * (BN / TN);
    static_assert(NT == 256, "need 256 threads");
    constexpr int LA = (BM * BK) / (4 * NT);
    constexpr int LB = (BN * BK) / (4 * NT);

    __shared__ __align__(16) float As[BK][BM];
    __shared__ __align__(16) float Bs[BK][BN];

    const int tid = threadIdx.x;
    const int bm = blockIdx.y * BM;
    const int bn = blockIdx.x * BN;
    const int tx = tid % (BN / TN);
    const int ty = tid / (BN / TN);

    float acc[TM][TN];
#pragma unroll
    for (int a = 0; a < TM; a++)
#pragma unroll
        for (int b = 0; b < TN; b++) acc[a][b] = 0.f;

    for (int k0 = 0; k0 < K; k0 += BK) {
#pragma unroll
        for (int l = 0; l < LA; l++) {
            int v = tid + l * NT;
            int r = v / (BK / 4);
            int kq = (v % (BK / 4)) * 4;
            int grow = bm + r;
            float4 av = make_float4(0.f, 0.f, 0.f, 0.f);
            if (grow < M)
                av = *(const float4*)(A + (size_t)grow * lda + k0 + kq);
            As[kq + 0][r] = av.x; As[kq + 1][r] = av.y;
            As[kq + 2][r] = av.z; As[kq + 3][r] = av.w;
        }
#pragma unroll
        for (int l = 0; l < LB; l++) {
            int v = tid + l * NT;
            int r = v / (BK / 4);
            int kq = (v % (BK / 4)) * 4;
            int gcol = bn + r;
            float4 wv = make_float4(0.f, 0.f, 0.f, 0.f);
            if (gcol < N)
                wv = *(const float4*)(W + (size_t)gcol * K + k0 + kq);
            Bs[kq + 0][r] = wv.x; Bs[kq + 1][r] = wv.y;
            Bs[kq + 2][r] = wv.z; Bs[kq + 3][r] = wv.w;
        }
        __syncthreads();

#pragma unroll
        for (int k = 0; k < BK; k++) {
            float ra[TM], rb[TN];
#pragma unroll
            for (int u = 0; u < TM / 4; u++)
                *(float4*)&ra[4 * u] = *(const float4*)&As[k][ty * TM + 4 * u];
#pragma unroll
            for (int u = 0; u < TN / 4; u++)
                *(float4*)&rb[4 * u] = *(const float4*)&Bs[k][tx * TN + 4 * u];
#pragma unroll
            for (int a = 0; a < TM; a++)
#pragma unroll
                for (int b = 0; b < TN; b++)
                    acc[a][b] = fmaf(ra[a], rb[b], acc[a][b]);
        }
        __syncthreads();
    }

#pragma unroll
    for (int a = 0; a < TM; a++) {
        int m = bm + ty * TM + a;
        if (m >= M) continue;
        bool last = ((m % Sl) == (Sl - 1));
#pragma unroll
        for (int b = 0; b < TN; b++) {
            int n = bn + tx * TN + b;
            if (n >= N) continue;
            float v = acc[a][b];
            if (EPI == 1) {
                v += bias[n];
                v = (v > 15.f) ? v : __logf(1.f + __expf(v));
                if (last) v *= lastscale[n];
            }
            C[(size_t)m * N + n] = v;
        }
    }
}

// ---------------------------------------------------------------------------
// Causal depthwise conv1d (K=4) + bias + SiLU — rolling-window.
// Emits both fp32 h (scan) and fp16 h16 (x_proj GEMM).
// ---------------------------------------------------------------------------
__global__ __launch_bounds__(256)
void conv_silu2(const float* __restrict__ proj,
                const float* __restrict__ cw,
                const float* __restrict__ cb,
                float* __restrict__ h,
                __half* __restrict__ h16)
{
    const int blk = blockIdx.x;                 // Bsz * (Sl/16)
    const int b = blk / (Sl / 16);
    const int st = (blk % (Sl / 16)) * 16;

#pragma unroll 1
    for (int ic = 0; ic < Iw / 256; ic++) {
        const int i = ic * 256 + threadIdx.x;
        float4 w = *(const float4*)(cw + (size_t)i * 4);
        const float bia = cb[i];
        const float* base = proj + ((size_t)b * Sl + st) * TWO_I + i;
        float* outp = h + ((size_t)b * Sl + st) * Iw + i;
        __half* outp16 = h16 + ((size_t)b * Sl + st) * Iw + i;

        float x3, x2, x1;
        if (st > 0) {
            x3 = base[-(size_t)3 * TWO_I];
            x2 = base[-(size_t)2 * TWO_I];
            x1 = base[-(size_t)1 * TWO_I];
        } else {
            x3 = x2 = x1 = 0.f;
        }
#pragma unroll
        for (int s = 0; s < 16; s++) {
            float x0 = base[(size_t)s * TWO_I];
            float acc = fmaf(w.w, x0, fmaf(w.z, x1, fmaf(w.y, x2, fmaf(w.x, x3, bia))));
            float sig = __fdividef(1.f, 1.f + __expf(-acc));
            float val = acc * sig;
            outp[(size_t)s * Iw] = val;
            outp16[(size_t)s * Iw] = __float2half_rn(val);
            x3 = x2; x2 = x1; x1 = x0;
        }
    }
}

// ---------------------------------------------------------------------------
// Selective scan v3: 4 states/lane, 8 channels/warp, 64-thread blocks.
// ---------------------------------------------------------------------------
#define SCT 64
#define NCH (Sl / SCT)

__global__ __launch_bounds__(64)
void scan_kernel3(const float* __restrict__ dt,
                  const float* __restrict__ h,
                  const float* __restrict__ ssm,
                  const float* __restrict__ proj,
                  const float* __restrict__ A_log,
                  const float* __restrict__ Dv,
                  const float* __restrict__ fg,
                  __half* __restrict__ y16)
{
    __shared__ __align__(16) float s_dt[2][SCT][16];
    __shared__ __align__(16) float s_h [2][SCT][16];
    __shared__ __align__(16) float s_g [2][SCT][16];
    __shared__ __align__(16) float s_B [2][SCT][16];
    __shared__ __align__(16) float s_C [2][SCT][16];
    __shared__ __align__(16) float s_y [SCT][16];
    __shared__ float s_D[16];

    const int tid = threadIdx.x;                // 0..63
    const int blk = blockIdx.x;                 // 0..191
    const int b = blk / (Iw / 16);
    const int i0 = (blk % (Iw / 16)) * 16;

    const int wid = tid >> 5;                   // 0..1
    const int lane = tid & 31;
    const int ci = wid * 8 + (lane >> 2);       // channel 0..15
    const int subl = lane & 3;                  // state quad

    if (tid < 16) s_D[tid] = Dv[i0 + tid];

    float An[4];
#pragma unroll
    for (int j = 0; j < 4; j++)
        An[j] = -__expf(A_log[(size_t)(i0 + ci) * Nst + subl * 4 + j]);
    float st4[4] = {0.f, 0.f, 0.f, 0.f};

    const size_t row0 = (size_t)b * Sl;

    const uint32_t a_dt = smem_u32(&s_dt[0][0][0]);
    const uint32_t a_h  = smem_u32(&s_h [0][0][0]);
    const uint32_t a_g  = smem_u32(&s_g [0][0][0]);
    const uint32_t a_B  = smem_u32(&s_B [0][0][0]);
    const uint32_t a_C  = smem_u32(&s_C [0][0][0]);
    const uint32_t stoff = SCT * 16 * 4;

    auto issue = [&](int st, int s0) {
#pragma unroll
        for (int l = 0; l < 4; l++) {
            int v = tid + l * 64;
            int r = v >> 2, c4 = (v & 3) * 4;
            size_t grow = row0 + s0 + r;
            uint32_t off = st * stoff + (r * 16 + c4) * 4;
            cp16(a_dt + off, dt   + grow * Iw + i0 + c4);
            cp16(a_h  + off, h    + grow * Iw + i0 + c4);
            cp16(a_g  + off, proj + grow * TWO_I + Iw + i0 + c4);
            cp16(a_B  + off, ssm  + grow * (Rr + 2 * Nst) + Rr + c4);
            cp16(a_C  + off, ssm  + grow * (Rr + 2 * Nst) + Rr + Nst + c4);
        }
        CP_COMMIT();
    };

    issue(0, 0);

    for (int ch = 0; ch < NCH; ch++) {
        const int st = ch & 1;
        const int s0 = ch * SCT;
        if (ch + 1 < NCH) { issue(st ^ 1, s0 + SCT); CP_WAIT(1); }
        else              { CP_WAIT(0); }
        __syncthreads();

#pragma unroll 4
        for (int s = 0; s < SCT; s++) {
            float dtv = s_dt[st][s][ci];
            float hv  = s_h [st][s][ci];
            float4 Bv = *(const float4*)&s_B[st][s][subl * 4];
            float4 Cv = *(const float4*)&s_C[st][s][subl * 4];
            float dth = dtv * hv;
            st4[0] = fmaf(__expf(An[0] * dtv), st4[0], dth * Bv.x);
            st4[1] = fmaf(__expf(An[1] * dtv), st4[1], dth * Bv.y);
            st4[2] = fmaf(__expf(An[2] * dtv), st4[2], dth * Bv.z);
            st4[3] = fmaf(__expf(An[3] * dtv), st4[3], dth * Bv.w);
            float part = st4[0] * Cv.x + st4[1] * Cv.y + st4[2] * Cv.z + st4[3] * Cv.w;
            part += __shfl_xor_sync(0xffffffffu, part, 2);
            part += __shfl_xor_sync(0xffffffffu, part, 1);
            if (subl == 0) s_y[s][ci] = part;
        }
        __syncthreads();

#pragma unroll
        for (int k = 0; k < 16; k++) {
            int idx = tid + k * 64;
            int r = idx >> 4, c = idx & 15;
            float hv = s_h[st][r][c];
            float g  = s_g[st][r][c];
            float sg = g * __fdividef(1.f, 1.f + __expf(-g));
            float val = (s_y[r][c] + hv * s_D[c]) * sg;
            if (s0 + r == Sl - 1) val *= fg[i0 + c];
            y16[(row0 + s0 + r) * Iw + i0 + c] = __float2half_rn(val);
        }
        __syncthreads();
    }
}

// ---------------------------------------------------------------------------
// Launch
// ---------------------------------------------------------------------------
extern "C" void kernel_launch(void* const* d_in, const int* in_sizes, int n_in,
                              void* d_out, int out_size)
{
    const float* x          = (const float*)d_in[0];
    const float* in_proj_w  = (const float*)d_in[1];
    const float* conv_w     = (const float*)d_in[2];
    const float* conv_b     = (const float*)d_in[3];
    const float* x_proj_w   = (const float*)d_in[4];
    const float* dt_proj_w  = (const float*)d_in[5];
    const float* dt_proj_b  = (const float*)d_in[6];
    const float* A_log      = (const float*)d_in[7];
    const float* Dv         = (const float*)d_in[8];
    const float* out_proj_w = (const float*)d_in[9];
    const float* alpha      = (const float*)d_in[10];
    const float* fg         = (const float*)d_in[11];
    float* out = (float*)d_out;

    float *proj, *h, *ssm, *dt;
    cudaGetSymbolAddress((void**)&proj, g_proj);
    cudaGetSymbolAddress((void**)&h,    g_h);
    cudaGetSymbolAddress((void**)&ssm,  g_ssm);
    cudaGetSymbolAddress((void**)&dt,   g_dt);

    __half *x16, *w1, *h16, *wx16, *y16, *w2;
    cudaGetSymbolAddress((void**)&x16,  g_x16);
    cudaGetSymbolAddress((void**)&w1,   g_w1);
    cudaGetSymbolAddress((void**)&h16,  g_h16);
    cudaGetSymbolAddress((void**)&wx16, g_wx16);
    cudaGetSymbolAddress((void**)&y16,  g_y16);
    cudaGetSymbolAddress((void**)&w2,   g_w2);

    constexpr int SMEM128 = 3 * (A_TILE_B + 128 * STRD * 2);   // 61440
    constexpr int SMEM64  = 3 * (A_TILE_B + 64 * STRD * 2);    // 46080
    cudaFuncSetAttribute(hmma_f16<128>, cudaFuncAttributeMaxDynamicSharedMemorySize, SMEM128);
    cudaFuncSetAttribute(hmma_f16<64>,  cudaFuncAttributeMaxDynamicSharedMemorySize, SMEM64);

    // 0-2) fp16 conversions needed for in_proj / x_proj
    {
        int n4 = (Ms * Dm) / 4;
        conv_f16<<<(n4 + 255) / 256, 256>>>(x, x16, n4);
        n4 = (TWO_I * Dm) / 4;
        conv_f16<<<(n4 + 255) / 256, 256>>>(in_proj_w, w1, n4);
        int nwx = (128 * Iw) / 4;
        conv_wx<<<(nwx + 255) / 256, 256>>>(x_proj_w, wx16);
    }

    // 3) in_proj (HMMA): proj[4096,3072] = x16 @ w1^T
    hmma_f16<128><<<dim3(TWO_I / 128, Ms / 128), 256, SMEM128>>>(
        x16, w1, proj, Ms, Dm, TWO_I, TWO_I);

    // 4) conv + SiLU (rolling window), emits h + h16
    conv_silu2<<<Bsz * (Sl / 16), 256>>>(proj, conv_w, conv_b, h, h16);

    // 5) x_proj (HMMA): ssm[4096,80] = h16 @ wx16^T  (N padded to 128, store-guarded)
    hmma_f16<128><<<dim3(1, Ms / 128), 256, SMEM128>>>(
        h16, wx16, ssm, Ms, Iw, Rr + 2 * Nst, Rr + 2 * Nst);

    // 6) dt_proj + fast softplus + alpha (fp32)
    sgemm_nt<64,64,16,4,4,1><<<dim3(Iw/64, Ms/64), 256>>>(
        ssm, dt_proj_w, dt, Ms, Iw, Rr, Rr + 2*Nst, dt_proj_b, alpha);

    // 7) scan v3 (emits fp16 y)
    scan_kernel3<<<(Bsz * Iw) / 16, 64>>>(dt, h, ssm, proj, A_log, Dv, fg, y16);

    // 8) convert out_proj weights
    {
        int n4 = (Dm * Iw) / 4;
        conv_f16<<<(n4 + 255) / 256, 256>>>(out_proj_w, w2, n4);
    }

    // 9) out_proj (HMMA, BN=64): out[4096,768] = y16 @ w2^T
    hmma_f16<64><<<dim3(Dm / 64, Ms / 128), 256, SMEM64>>>(
        y16, w2, out, Ms, Iw, Dm, Dm);
}

// round 10
// speedup vs baseline: 2.3862x; 1.0162x over previous
#include <cuda_runtime.h>
#include <cuda_bf16.h>
#include <cuda_fp16.h>
#include <cstdint>

// Problem constants
#define Bsz 2
#define Sl  2048
#define Dm  768
#define Iw  1536
#define Nst 16
#define Rr  48
#define Ms  (Bsz * Sl)          // 4096 rows
#define TWO_I (2 * Iw)          // 3072

// ---------------------------------------------------------------------------
// Scratch (device globals)
// ---------------------------------------------------------------------------
__device__ float g_proj[(size_t)Ms * TWO_I];
__device__ float g_ssm [(size_t)Ms * (Rr + 2 * Nst)];
__device__ float g_dt  [(size_t)Ms * Iw];

__device__ __half g_x16 [(size_t)Ms * Dm];
__device__ __half g_w1  [(size_t)TWO_I * Dm];
__device__ __half g_h16 [(size_t)Ms * Iw];
__device__ __half g_wx16[(size_t)128 * Iw];     // x_proj_w padded 80->128 rows
__device__ __half g_y16 [(size_t)Ms * Iw];
__device__ __half g_w2  [(size_t)Dm * Iw];

// ---------------------------------------------------------------------------
// Helpers
// ---------------------------------------------------------------------------
__device__ __forceinline__ uint32_t smem_u32(const void* p) {
    uint32_t a;
    asm("{ .reg .u64 t; cvta.to.shared.u64 t, %1; cvt.u32.u64 %0, t; }" : "=r"(a) : "l"(p));
    return a;
}
__device__ __forceinline__ void cp16(uint32_t saddr, const void* gsrc) {
    asm volatile("cp.async.cg.shared.global [%0], [%1], 16;" :: "r"(saddr), "l"(gsrc));
}
#define CP_COMMIT() asm volatile("cp.async.commit_group;" ::: "memory")
#define CP_WAIT(n)  asm volatile("cp.async.wait_group %0;" :: "n"(n) : "memory")

__device__ __forceinline__ void ldm_x4(uint32_t* r, uint32_t addr) {
    asm volatile("ldmatrix.sync.aligned.m8n8.x4.shared.b16 {%0,%1,%2,%3}, [%4];"
                 : "=r"(r[0]), "=r"(r[1]), "=r"(r[2]), "=r"(r[3]) : "r"(addr));
}
__device__ __forceinline__ void ldm_x2(uint32_t* r, uint32_t addr) {
    asm volatile("ldmatrix.sync.aligned.m8n8.x2.shared.b16 {%0,%1}, [%2];"
                 : "=r"(r[0]), "=r"(r[1]) : "r"(addr));
}
__device__ __forceinline__ void mma16816(float* c, const uint32_t* a, const uint32_t* b) {
    asm volatile("mma.sync.aligned.m16n8k16.row.col.f32.f16.f16.f32 "
                 "{%0,%1,%2,%3}, {%4,%5,%6,%7}, {%8,%9}, {%0,%1,%2,%3};"
                 : "+f"(c[0]), "+f"(c[1]), "+f"(c[2]), "+f"(c[3])
                 : "r"(a[0]), "r"(a[1]), "r"(a[2]), "r"(a[3]), "r"(b[0]), "r"(b[1]));
}

// ---------------------------------------------------------------------------
// HMMA fp16 GEMM: C[M, ldC] (cols < Nstore) = A16[M,K] @ W16[.,K]^T
// 128xBN CTA tile, BK=32, 256 threads, 3-stage cp.async, one sync per chunk.
// ---------------------------------------------------------------------------
#define STRD 40
#define A_TILE_B (128 * STRD * 2)           // 10240

template<int BN>
__global__ __launch_bounds__(256, (BN == 64 ? 3 : 2))
void hmma_f16(const __half* __restrict__ A16, const __half* __restrict__ W16,
              float* __restrict__ C, int M, int K, int ldC, int Nstore)
{
    constexpr int NWN = BN / 32;            // warps along n
    constexpr int NWM = 8 / NWN;            // warps along m
    constexpr int MT  = 128 / (NWM * 16);   // 16-row m-tiles per warp
    constexpr int W_TILE_B = BN * STRD * 2;
    constexpr int STAGE = A_TILE_B + W_TILE_B;
    constexpr int NSLOT = (128 + BN) * 4;   // 16B slots per stage

    extern __shared__ __align__(16) char smem[];
    const uint32_t sb = smem_u32(smem);
    const int tid = threadIdx.x;
    const int wid = tid >> 5, lane = tid & 31;
    const int warp_m = wid / NWN, warp_n = wid % NWN;
    const int bm = blockIdx.y * 128, bn = blockIdx.x * BN;

    auto load_stage = [&](int st, int k0) {
#pragma unroll
        for (int v = tid; v < NSLOT; v += 256) {
            int row, c16;
            const __half* src;
            uint32_t base;
            if (v < 512) {
                row = v >> 2; c16 = v & 3;
                src = A16 + (size_t)(bm + row) * K + k0 + c16 * 8;
                base = 0;
            } else {
                int u = v - 512;
                row = u >> 2; c16 = u & 3;
                src = W16 + (size_t)(bn + row) * K + k0 + c16 * 8;
                base = A_TILE_B;
            }
            cp16(sb + st * STAGE + base + (row * STRD + c16 * 8) * 2, src);
        }
        CP_COMMIT();
    };

    float acc[MT][4][4];
#pragma unroll
    for (int i = 0; i < MT; i++)
#pragma unroll
        for (int j = 0; j < 4; j++)
#pragma unroll
            for (int k = 0; k < 4; k++) acc[i][j][k] = 0.f;

    const int nch = K >> 5;
    load_stage(0, 0);
    if (nch > 1) load_stage(1, 32);

    const int a_r = warp_m * (MT * 16) + (lane & 15);
    const int a_k = (lane >> 4) * 8;
    const int b_r = warp_n * 32 + (lane & 7);
    const int b_k = ((lane >> 3) & 1) * 8;

    for (int ch = 0; ch < nch; ch++) {
        const int st = ch % 3;
        if (ch == nch - 1) { CP_WAIT(0); } else { CP_WAIT(1); }
        __syncthreads();
        if (ch + 2 < nch) load_stage((ch + 2) % 3, (ch + 2) << 5);

        const uint32_t aB = sb + st * STAGE;
        const uint32_t wB = aB + A_TILE_B;

#pragma unroll
        for (int kk = 0; kk < 2; kk++) {
            uint32_t a[MT][4], b[4][2];
#pragma unroll
            for (int mt = 0; mt < MT; mt++)
                ldm_x4(a[mt], aB + ((a_r + mt * 16) * STRD + a_k + kk * 16) * 2);
#pragma unroll
            for (int nt = 0; nt < 4; nt++)
                ldm_x2(b[nt], wB + ((b_r + nt * 8) * STRD + b_k + kk * 16) * 2);
#pragma unroll
            for (int mt = 0; mt < MT; mt++)
#pragma unroll
                for (int nt = 0; nt < 4; nt++)
                    mma16816(acc[mt][nt], a[mt], b[nt]);
        }
    }

    const int er = bm + warp_m * (MT * 16) + (lane >> 2);
    const int ec = bn + warp_n * 32 + (lane & 3) * 2;
#pragma unroll
    for (int mt = 0; mt < MT; mt++)
#pragma unroll
        for (int nt = 0; nt < 4; nt++) {
            int r = er + mt * 16;
            int c = ec + nt * 8;
            if (c < Nstore) {
                *(float2*)&C[(size_t)r * ldC + c]       = make_float2(acc[mt][nt][0], acc[mt][nt][1]);
                *(float2*)&C[(size_t)(r + 8) * ldC + c] = make_float2(acc[mt][nt][2], acc[mt][nt][3]);
            }
        }
}

// ---------------------------------------------------------------------------
// Fused prep: all fp32->fp16 conversions in one launch.
// Regions: x->x16 | in_proj_w->w1 | out_proj_w->w2 | x_proj_w->wx16 (padded)
// ---------------------------------------------------------------------------
#define PN0 ((Ms * Dm) / 4)
#define PN1 ((TWO_I * Dm) / 4)
#define PN2 ((Dm * Iw) / 4)
#define PN3 ((128 * Iw) / 4)
#define PTOT (PN0 + PN1 + PN2 + PN3)

__global__ __launch_bounds__(256)
void prep_f16(const float* __restrict__ x, const float* __restrict__ w1f,
              const float* __restrict__ w2f, const float* __restrict__ wxf,
              __half* __restrict__ x16, __half* __restrict__ w1,
              __half* __restrict__ w2, __half* __restrict__ wx16)
{
    int i = blockIdx.x * 256 + threadIdx.x;
    if (i >= PTOT) return;
    const float* src;
    __half* dst;
    int j;
    bool zero = false;
    if (i < PN0) { j = i; src = x; dst = x16; }
    else if (i < PN0 + PN1) { j = i - PN0; src = w1f; dst = w1; }
    else if (i < PN0 + PN1 + PN2) { j = i - PN0 - PN1; src = w2f; dst = w2; }
    else {
        j = i - PN0 - PN1 - PN2; src = wxf; dst = wx16;
        zero = ((j * 4) / Iw) >= (Rr + 2 * Nst);
    }
    __half2* op = (__half2*)(dst + (size_t)j * 4);
    if (zero) {
        op[0] = __half2(__half(0.f), __half(0.f));
        op[1] = __half2(__half(0.f), __half(0.f));
    } else {
        float4 v = ((const float4*)src)[j];
        op[0] = __floats2half2_rn(v.x, v.y);
        op[1] = __floats2half2_rn(v.z, v.w);
    }
}

// ---------------------------------------------------------------------------
// fp32 tiled SGEMM (dt_proj). EPI 1: fast softplus + alpha on last step.
// ---------------------------------------------------------------------------
template<int BM, int BN, int BK, int TM, int TN, int EPI>
__global__ __launch_bounds__(256)
void sgemm_nt(const float* __restrict__ A, const float* __restrict__ W,
              float* __restrict__ C, int M, int N, int K, int lda,
              const float* __restrict__ bias,
              const float* __restrict__ lastscale)
{
    constexpr int NT = (BM / TM) * (BN / TN);
    static_assert(NT == 256, "need 256 threads");
    constexpr int LA = (BM * BK) / (4 * NT);
    constexpr int LB = (BN * BK) / (4 * NT);

    __shared__ __align__(16) float As[BK][BM];
    __shared__ __align__(16) float Bs[BK][BN];

    const int tid = threadIdx.x;
    const int bm = blockIdx.y * BM;
    const int bn = blockIdx.x * BN;
    const int tx = tid % (BN / TN);
    const int ty = tid / (BN / TN);

    float acc[TM][TN];
#pragma unroll
    for (int a = 0; a < TM; a++)
#pragma unroll
        for (int b = 0; b < TN; b++) acc[a][b] = 0.f;

    for (int k0 = 0; k0 < K; k0 += BK) {
#pragma unroll
        for (int l = 0; l < LA; l++) {
            int v = tid + l * NT;
            int r = v / (BK / 4);
            int kq = (v % (BK / 4)) * 4;
            int grow = bm + r;
            float4 av = make_float4(0.f, 0.f, 0.f, 0.f);
            if (grow < M)
                av = *(const float4*)(A + (size_t)grow * lda + k0 + kq);
            As[kq + 0][r] = av.x; As[kq + 1][r] = av.y;
            As[kq + 2][r] = av.z; As[kq + 3][r] = av.w;
        }
#pragma unroll
        for (int l = 0; l < LB; l++) {
            int v = tid + l * NT;
            int r = v / (BK / 4);
            int kq = (v % (BK / 4)) * 4;
            int gcol = bn + r;
            float4 wv = make_float4(0.f, 0.f, 0.f, 0.f);
            if (gcol < N)
                wv = *(const float4*)(W + (size_t)gcol * K + k0 + kq);
            Bs[kq + 0][r] = wv.x; Bs[kq + 1][r] = wv.y;
            Bs[kq + 2][r] = wv.z; Bs[kq + 3][r] = wv.w;
        }
        __syncthreads();

#pragma unroll
        for (int k = 0; k < BK; k++) {
            float ra[TM], rb[TN];
#pragma unroll
            for (int u = 0; u < TM / 4; u++)
                *(float4*)&ra[4 * u] = *(const float4*)&As[k][ty * TM + 4 * u];
#pragma unroll
            for (int u = 0; u < TN / 4; u++)
                *(float4*)&rb[4 * u] = *(const float4*)&Bs[k][tx * TN + 4 * u];
#pragma unroll
            for (int a = 0; a < TM; a++)
#pragma unroll
                for (int b = 0; b < TN; b++)
                    acc[a][b] = fmaf(ra[a], rb[b], acc[a][b]);
        }
        __syncthreads();
    }

#pragma unroll
    for (int a = 0; a < TM; a++) {
        int m = bm + ty * TM + a;
        if (m >= M) continue;
        bool last = ((m % Sl) == (Sl - 1));
#pragma unroll
        for (int b = 0; b < TN; b++) {
            int n = bn + tx * TN + b;
            if (n >= N) continue;
            float v = acc[a][b];
            if (EPI == 1) {
                v += bias[n];
                v = (v > 15.f) ? v : __logf(1.f + __expf(v));
                if (last) v *= lastscale[n];
            }
            C[(size_t)m * N + n] = v;
        }
    }
}

// ---------------------------------------------------------------------------
// Causal depthwise conv1d (K=4) + bias + SiLU — rolling-window; emits h16 only.
// ---------------------------------------------------------------------------
__global__ __launch_bounds__(256)
void conv_silu2(const float* __restrict__ proj,
                const float* __restrict__ cw,
                const float* __restrict__ cb,
                __half* __restrict__ h16)
{
    const int blk = blockIdx.x;                 // Bsz * (Sl/16)
    const int b = blk / (Sl / 16);
    const int st = (blk % (Sl / 16)) * 16;

#pragma unroll 1
    for (int ic = 0; ic < Iw / 256; ic++) {
        const int i = ic * 256 + threadIdx.x;
        float4 w = *(const float4*)(cw + (size_t)i * 4);
        const float bia = cb[i];
        const float* base = proj + ((size_t)b * Sl + st) * TWO_I + i;
        __half* outp16 = h16 + ((size_t)b * Sl + st) * Iw + i;

        float x3, x2, x1;
        if (st > 0) {
            x3 = base[-(size_t)3 * TWO_I];
            x2 = base[-(size_t)2 * TWO_I];
            x1 = base[-(size_t)1 * TWO_I];
        } else {
            x3 = x2 = x1 = 0.f;
        }
#pragma unroll
        for (int s = 0; s < 16; s++) {
            float x0 = base[(size_t)s * TWO_I];
            float acc = fmaf(w.w, x0, fmaf(w.z, x1, fmaf(w.y, x2, fmaf(w.x, x3, bia))));
            float sig = __fdividef(1.f, 1.f + __expf(-acc));
            outp16[(size_t)s * Iw] = __float2half_rn(acc * sig);
            x3 = x2; x2 = x1; x1 = x0;
        }
    }
}

// ---------------------------------------------------------------------------
// Selective scan v4: 2 states/lane, 8 lanes/channel, 16 ch/block, 128 threads.
// Reads h16; emits fp16 y (fused D, silu(gate), fg epilogue).
// ---------------------------------------------------------------------------
#define SCT 64
#define NCH (Sl / SCT)

__global__ __launch_bounds__(128)
void scan_kernel4(const float* __restrict__ dt,
                  const __half* __restrict__ h16,
                  const float* __restrict__ ssm,
                  const float* __restrict__ proj,
                  const float* __restrict__ A_log,
                  const float* __restrict__ Dv,
                  const float* __restrict__ fg,
                  __half* __restrict__ y16)
{
    __shared__ __align__(16) float  s_dt[2][SCT][16];
    __shared__ __align__(16) float  s_g [2][SCT][16];
    __shared__ __align__(16) float  s_B [2][SCT][16];
    __shared__ __align__(16) float  s_C [2][SCT][16];
    __shared__ __align__(16) __half s_h [2][SCT][16];
    __shared__ __align__(16) float  s_y [SCT][16];
    __shared__ float s_D[16];

    const int tid = threadIdx.x;                // 0..127
    const int blk = blockIdx.x;                 // 0..191
    const int b = blk / (Iw / 16);
    const int i0 = (blk % (Iw / 16)) * 16;

    const int wid = tid >> 5;                   // 0..3
    const int lane = tid & 31;
    const int ci = wid * 4 + (lane >> 3);       // channel 0..15
    const int sl = lane & 7;                    // 2 states: sl*2, sl*2+1

    if (tid < 16) s_D[tid] = Dv[i0 + tid];

    float An0 = -__expf(A_log[(size_t)(i0 + ci) * Nst + sl * 2]);
    float An1 = -__expf(A_log[(size_t)(i0 + ci) * Nst + sl * 2 + 1]);
    float st0 = 0.f, st1 = 0.f;

    const size_t row0 = (size_t)b * Sl;

    const uint32_t a_dt = smem_u32(&s_dt[0][0][0]);
    const uint32_t a_g  = smem_u32(&s_g [0][0][0]);
    const uint32_t a_B  = smem_u32(&s_B [0][0][0]);
    const uint32_t a_C  = smem_u32(&s_C [0][0][0]);
    const uint32_t a_h  = smem_u32(&s_h [0][0][0]);
    const uint32_t stoff  = SCT * 16 * 4;       // fp32 stage bytes
    const uint32_t stoffh = SCT * 16 * 2;       // fp16 stage bytes

    auto issue = [&](int st, int s0) {
        // fp32 arrays: 256 slots each (r = v>>2, c4 = (v&3)*4)
#pragma unroll
        for (int l = 0; l < 2; l++) {
            int v = tid + l * 128;
            int r = v >> 2, c4 = (v & 3) * 4;
            size_t grow = row0 + s0 + r;
            uint32_t off = st * stoff + (r * 16 + c4) * 4;
            cp16(a_dt + off, dt   + grow * Iw + i0 + c4);
            cp16(a_g  + off, proj + grow * TWO_I + Iw + i0 + c4);
            cp16(a_B  + off, ssm  + grow * (Rr + 2 * Nst) + Rr + c4);
            cp16(a_C  + off, ssm  + grow * (Rr + 2 * Nst) + Rr + Nst + c4);
        }
        // h16: 128 slots (r = v>>1, c8 = (v&1)*8)
        {
            int v = tid;
            int r = v >> 1, c8 = (v & 1) * 8;
            size_t grow = row0 + s0 + r;
            cp16(a_h + st * stoffh + (r * 16 + c8) * 2, h16 + grow * Iw + i0 + c8);
        }
        CP_COMMIT();
    };

    issue(0, 0);

    for (int ch = 0; ch < NCH; ch++) {
        const int st = ch & 1;
        const int s0 = ch * SCT;
        if (ch + 1 < NCH) { issue(st ^ 1, s0 + SCT); CP_WAIT(1); }
        else              { CP_WAIT(0); }
        __syncthreads();

#pragma unroll 4
        for (int s = 0; s < SCT; s++) {
            float dtv = s_dt[st][s][ci];
            float hv  = __half2float(s_h[st][s][ci]);
            float2 Bv = *(const float2*)&s_B[st][s][sl * 2];
            float2 Cv = *(const float2*)&s_C[st][s][sl * 2];
            float dth = dtv * hv;
            st0 = fmaf(__expf(An0 * dtv), st0, dth * Bv.x);
            st1 = fmaf(__expf(An1 * dtv), st1, dth * Bv.y);
            float part = st0 * Cv.x + st1 * Cv.y;
            part += __shfl_xor_sync(0xffffffffu, part, 4);
            part += __shfl_xor_sync(0xffffffffu, part, 2);
            part += __shfl_xor_sync(0xffffffffu, part, 1);
            if (sl == 0) s_y[s][ci] = part;
        }
        __syncthreads();

        // parallel epilogue + fp16 writeout: 1024 elems / 128 thr = 8
#pragma unroll
        for (int k = 0; k < 8; k++) {
            int idx = tid + k * 128;
            int r = idx >> 4, c = idx & 15;
            float hv = __half2float(s_h[st][r][c]);
            float g  = s_g[st][r][c];
            float sg = g * __fdividef(1.f, 1.f + __expf(-g));
            float val = (s_y[r][c] + hv * s_D[c]) * sg;
            if (s0 + r == Sl - 1) val *= fg[i0 + c];
            y16[(row0 + s0 + r) * Iw + i0 + c] = __float2half_rn(val);
        }
        __syncthreads();
    }
}

// ---------------------------------------------------------------------------
// Launch
// ---------------------------------------------------------------------------
extern "C" void kernel_launch(void* const* d_in, const int* in_sizes, int n_in,
                              void* d_out, int out_size)
{
    const float* x          = (const float*)d_in[0];
    const float* in_proj_w  = (const float*)d_in[1];
    const float* conv_w     = (const float*)d_in[2];
    const float* conv_b     = (const float*)d_in[3];
    const float* x_proj_w   = (const float*)d_in[4];
    const float* dt_proj_w  = (const float*)d_in[5];
    const float* dt_proj_b  = (const float*)d_in[6];
    const float* A_log      = (const float*)d_in[7];
    const float* Dv         = (const float*)d_in[8];
    const float* out_proj_w = (const float*)d_in[9];
    const float* alpha      = (const float*)d_in[10];
    const float* fg         = (const float*)d_in[11];
    float* out = (float*)d_out;

    float *proj, *ssm, *dt;
    cudaGetSymbolAddress((void**)&proj, g_proj);
    cudaGetSymbolAddress((void**)&ssm,  g_ssm);
    cudaGetSymbolAddress((void**)&dt,   g_dt);

    __half *x16, *w1, *h16, *wx16, *y16, *w2;
    cudaGetSymbolAddress((void**)&x16,  g_x16);
    cudaGetSymbolAddress((void**)&w1,   g_w1);
    cudaGetSymbolAddress((void**)&h16,  g_h16);
    cudaGetSymbolAddress((void**)&wx16, g_wx16);
    cudaGetSymbolAddress((void**)&y16,  g_y16);
    cudaGetSymbolAddress((void**)&w2,   g_w2);

    constexpr int SMEM128 = 3 * (A_TILE_B + 128 * STRD * 2);   // 61440
    constexpr int SMEM64  = 3 * (A_TILE_B + 64 * STRD * 2);    // 46080
    cudaFuncSetAttribute(hmma_f16<128>, cudaFuncAttributeMaxDynamicSharedMemorySize, SMEM128);
    cudaFuncSetAttribute(hmma_f16<64>,  cudaFuncAttributeMaxDynamicSharedMemorySize, SMEM64);

    // 0) all fp16 conversions in one launch
    prep_f16<<<(PTOT + 255) / 256, 256>>>(x, in_proj_w, out_proj_w, x_proj_w,
                                          x16, w1, w2, wx16);

    // 1) in_proj (HMMA): proj[4096,3072] = x16 @ w1^T
    hmma_f16<128><<<dim3(TWO_I / 128, Ms / 128), 256, SMEM128>>>(
        x16, w1, proj, Ms, Dm, TWO_I, TWO_I);

    // 2) conv + SiLU (rolling window) -> h16
    conv_silu2<<<Bsz * (Sl / 16), 256>>>(proj, conv_w, conv_b, h16);

    // 3) x_proj (HMMA, BN=64): ssm[4096,80] = h16 @ wx16^T (cols guarded)
    hmma_f16<64><<<dim3(2, Ms / 128), 256, SMEM64>>>(
        h16, wx16, ssm, Ms, Iw, Rr + 2 * Nst, Rr + 2 * Nst);

    // 4) dt_proj + fast softplus + alpha (fp32)
    sgemm_nt<64,64,16,4,4,1><<<dim3(Iw/64, Ms/64), 256>>>(
        ssm, dt_proj_w, dt, Ms, Iw, Rr, Rr + 2*Nst, dt_proj_b, alpha);

    // 5) scan v4 (reads h16, emits fp16 y)
    scan_kernel4<<<(Bsz * Iw) / 16, 128>>>(dt, h16, ssm, proj, A_log, Dv, fg, y16);

    // 6) out_proj (HMMA, BN=64): out[4096,768] = y16 @ w2^T
    hmma_f16<64><<<dim3(Dm / 64, Ms / 128), 256, SMEM64>>>(
        y16, w2, out, Ms, Iw, Dm, Dm);
}

// round 11
// speedup vs baseline: 2.5000x; 1.0477x over previous
#include <cuda_runtime.h>
#include <cuda_bf16.h>
#include <cuda_fp16.h>
#include <cstdint>

// Problem constants
#define Bsz 2
#define Sl  2048
#define Dm  768
#define Iw  1536
#define Nst 16
#define Rr  48
#define Ms  (Bsz * Sl)          // 4096 rows
#define TWO_I (2 * Iw)          // 3072

// ---------------------------------------------------------------------------
// Scratch (device globals)
// ---------------------------------------------------------------------------
__device__ float g_gate[(size_t)Ms * Iw];       // gate half of in_proj (fp32)
__device__ float g_ssm [(size_t)Ms * (Rr + 2 * Nst)];
__device__ float g_dt  [(size_t)Ms * Iw];

__device__ __half g_x16  [(size_t)Ms * Dm];
__device__ __half g_w1   [(size_t)TWO_I * Dm];
__device__ __half g_hid16[(size_t)Ms * Iw];     // pre-conv hidden (fp16)
__device__ __half g_h16  [(size_t)Ms * Iw];     // post-conv h (fp16)
__device__ __half g_wx16 [(size_t)128 * Iw];    // x_proj_w padded 80->128 rows
__device__ __half g_ts16 [(size_t)Ms * 64];     // time-step part, K padded 48->64
__device__ __half g_wdt16[(size_t)Iw * 64];     // dt_proj_w padded 48->64 cols
__device__ __half g_y16  [(size_t)Ms * Iw];
__device__ __half g_w2   [(size_t)Dm * Iw];

// ---------------------------------------------------------------------------
// Helpers
// ---------------------------------------------------------------------------
__device__ __forceinline__ uint32_t smem_u32(const void* p) {
    uint32_t a;
    asm("{ .reg .u64 t; cvta.to.shared.u64 t, %1; cvt.u32.u64 %0, t; }" : "=r"(a) : "l"(p));
    return a;
}
__device__ __forceinline__ void cp16(uint32_t saddr, const void* gsrc) {
    asm volatile("cp.async.cg.shared.global [%0], [%1], 16;" :: "r"(saddr), "l"(gsrc));
}
#define CP_COMMIT() asm volatile("cp.async.commit_group;" ::: "memory")
#define CP_WAIT(n)  asm volatile("cp.async.wait_group %0;" :: "n"(n) : "memory")

__device__ __forceinline__ void ldm_x4(uint32_t* r, uint32_t addr) {
    asm volatile("ldmatrix.sync.aligned.m8n8.x4.shared.b16 {%0,%1,%2,%3}, [%4];"
                 : "=r"(r[0]), "=r"(r[1]), "=r"(r[2]), "=r"(r[3]) : "r"(addr));
}
__device__ __forceinline__ void ldm_x2(uint32_t* r, uint32_t addr) {
    asm volatile("ldmatrix.sync.aligned.m8n8.x2.shared.b16 {%0,%1}, [%2];"
                 : "=r"(r[0]), "=r"(r[1]) : "r"(addr));
}
__device__ __forceinline__ void mma16816(float* c, const uint32_t* a, const uint32_t* b) {
    asm volatile("mma.sync.aligned.m16n8k16.row.col.f32.f16.f16.f32 "
                 "{%0,%1,%2,%3}, {%4,%5,%6,%7}, {%8,%9}, {%0,%1,%2,%3};"
                 : "+f"(c[0]), "+f"(c[1]), "+f"(c[2]), "+f"(c[3])
                 : "r"(a[0]), "r"(a[1]), "r"(a[2]), "r"(a[3]), "r"(b[0]), "r"(b[1]));
}

// ---------------------------------------------------------------------------
// HMMA fp16 GEMM with fused epilogues.
// EPI 0: plain fp32 store (cols < Nstore)
// EPI 1: x_proj  — fp32 ssm (cols < Nstore) + fp16 ts16 (bn==0, col<48, pad 0)
// EPI 2: dt_proj — softplus(acc + bias), alpha on last timestep, fp32 store
// EPI 3: in_proj — cols < Iw -> fp16 aux (hidden); cols >= Iw -> fp32 C (gate)
// ---------------------------------------------------------------------------
#define STRD 40
#define A_TILE_B (128 * STRD * 2)           // 10240

template<int BN, int EPI>
__global__ __launch_bounds__(256, (BN == 64 ? 3 : 2))
void hmma_f16(const __half* __restrict__ A16, const __half* __restrict__ W16,
              float* __restrict__ C, int M, int K, int ldC, int Nstore,
              const float* __restrict__ bias, const float* __restrict__ lastscale,
              __half* __restrict__ aux)
{
    constexpr int NWN = BN / 32;            // warps along n
    constexpr int NWM = 8 / NWN;            // warps along m
    constexpr int MT  = 128 / (NWM * 16);   // 16-row m-tiles per warp
    constexpr int W_TILE_B = BN * STRD * 2;
    constexpr int STAGE = A_TILE_B + W_TILE_B;
    constexpr int NSLOT = (128 + BN) * 4;   // 16B slots per stage

    extern __shared__ __align__(16) char smem[];
    const uint32_t sb = smem_u32(smem);
    const int tid = threadIdx.x;
    const int wid = tid >> 5, lane = tid & 31;
    const int warp_m = wid / NWN, warp_n = wid % NWN;
    const int bm = blockIdx.y * 128, bn = blockIdx.x * BN;

    auto load_stage = [&](int st, int k0) {
#pragma unroll
        for (int v = tid; v < NSLOT; v += 256) {
            int row, c16;
            const __half* src;
            uint32_t base;
            if (v < 512) {
                row = v >> 2; c16 = v & 3;
                src = A16 + (size_t)(bm + row) * K + k0 + c16 * 8;
                base = 0;
            } else {
                int u = v - 512;
                row = u >> 2; c16 = u & 3;
                src = W16 + (size_t)(bn + row) * K + k0 + c16 * 8;
                base = A_TILE_B;
            }
            cp16(sb + st * STAGE + base + (row * STRD + c16 * 8) * 2, src);
        }
        CP_COMMIT();
    };

    float acc[MT][4][4];
#pragma unroll
    for (int i = 0; i < MT; i++)
#pragma unroll
        for (int j = 0; j < 4; j++)
#pragma unroll
            for (int k = 0; k < 4; k++) acc[i][j][k] = 0.f;

    const int nch = K >> 5;
    load_stage(0, 0);
    if (nch > 1) load_stage(1, 32);

    const int a_r = warp_m * (MT * 16) + (lane & 15);
    const int a_k = (lane >> 4) * 8;
    const int b_r = warp_n * 32 + (lane & 7);
    const int b_k = ((lane >> 3) & 1) * 8;

    for (int ch = 0; ch < nch; ch++) {
        const int st = ch % 3;
        if (ch == nch - 1) { CP_WAIT(0); } else { CP_WAIT(1); }
        __syncthreads();
        if (ch + 2 < nch) load_stage((ch + 2) % 3, (ch + 2) << 5);

        const uint32_t aB = sb + st * STAGE;
        const uint32_t wB = aB + A_TILE_B;

#pragma unroll
        for (int kk = 0; kk < 2; kk++) {
            uint32_t a[MT][4], b[4][2];
#pragma unroll
            for (int mt = 0; mt < MT; mt++)
                ldm_x4(a[mt], aB + ((a_r + mt * 16) * STRD + a_k + kk * 16) * 2);
#pragma unroll
            for (int nt = 0; nt < 4; nt++)
                ldm_x2(b[nt], wB + ((b_r + nt * 8) * STRD + b_k + kk * 16) * 2);
#pragma unroll
            for (int mt = 0; mt < MT; mt++)
#pragma unroll
                for (int nt = 0; nt < 4; nt++)
                    mma16816(acc[mt][nt], a[mt], b[nt]);
        }
    }

    const int er = bm + warp_m * (MT * 16) + (lane >> 2);
    const int ec = bn + warp_n * 32 + (lane & 3) * 2;
#pragma unroll
    for (int mt = 0; mt < MT; mt++)
#pragma unroll
        for (int nt = 0; nt < 4; nt++) {
            int r0 = er + mt * 16;
            int r1 = r0 + 8;
            int c = ec + nt * 8;
            float* ac = acc[mt][nt];
            if (EPI == 0) {
                *(float2*)&C[(size_t)r0 * ldC + c] = make_float2(ac[0], ac[1]);
                *(float2*)&C[(size_t)r1 * ldC + c] = make_float2(ac[2], ac[3]);
            } else if (EPI == 1) {
                if (c < Nstore) {
                    *(float2*)&C[(size_t)r0 * ldC + c] = make_float2(ac[0], ac[1]);
                    *(float2*)&C[(size_t)r1 * ldC + c] = make_float2(ac[2], ac[3]);
                }
                if (blockIdx.x == 0) {   // c < 64; pad cols >= 48 with zero
                    __half2 z = __half2(__half(0.f), __half(0.f));
                    __half2 h0 = (c < Rr) ? __floats2half2_rn(ac[0], ac[1]) : z;
                    __half2 h1 = (c < Rr) ? __floats2half2_rn(ac[2], ac[3]) : z;
                    *(__half2*)&aux[(size_t)r0 * 64 + c] = h0;
                    *(__half2*)&aux[(size_t)r1 * 64 + c] = h1;
                }
            } else if (EPI == 2) {
                float u[4] = {ac[0], ac[1], ac[2], ac[3]};
#pragma unroll
                for (int e = 0; e < 4; e++) {
                    int col = c + (e & 1);
                    int row = (e < 2) ? r0 : r1;
                    float v = u[e] + bias[col];
                    v = (v > 15.f) ? v : __logf(1.f + __expf(v));
                    if ((row & (Sl - 1)) == Sl - 1) v *= lastscale[col];
                    u[e] = v;
                }
                *(float2*)&C[(size_t)r0 * ldC + c] = make_float2(u[0], u[1]);
                *(float2*)&C[(size_t)r1 * ldC + c] = make_float2(u[2], u[3]);
            } else {  // EPI == 3
                if (c < Iw) {
                    *(__half2*)&aux[(size_t)r0 * Iw + c] = __floats2half2_rn(ac[0], ac[1]);
                    *(__half2*)&aux[(size_t)r1 * Iw + c] = __floats2half2_rn(ac[2], ac[3]);
                } else {
                    int cg = c - Iw;
                    *(float2*)&C[(size_t)r0 * Iw + cg] = make_float2(ac[0], ac[1]);
                    *(float2*)&C[(size_t)r1 * Iw + cg] = make_float2(ac[2], ac[3]);
                }
            }
        }
}

// ---------------------------------------------------------------------------
// Fused prep: all fp32->fp16 conversions in one launch.
// x->x16 | in_proj_w->w1 | out_proj_w->w2 | x_proj_w->wx16 (pad) | dt_proj_w->wdt16 (pad)
// ---------------------------------------------------------------------------
#define PN0 ((Ms * Dm) / 4)
#define PN1 ((TWO_I * Dm) / 4)
#define PN2 ((Dm * Iw) / 4)
#define PN3 ((128 * Iw) / 4)
#define PN4 ((Iw * 64) / 4)
#define PTOT (PN0 + PN1 + PN2 + PN3 + PN4)

__global__ __launch_bounds__(256)
void prep_f16(const float* __restrict__ x, const float* __restrict__ w1f,
              const float* __restrict__ w2f, const float* __restrict__ wxf,
              const float* __restrict__ wdtf,
              __half* __restrict__ x16, __half* __restrict__ w1,
              __half* __restrict__ w2, __half* __restrict__ wx16,
              __half* __restrict__ wdt16)
{
    int i = blockIdx.x * 256 + threadIdx.x;
    if (i >= PTOT) return;
    const float* src;
    __half* dst;
    long j;
    long srcoff;
    bool zero = false;
    if (i < PN0) { j = i; srcoff = j * 4; src = x; dst = x16; }
    else if (i < PN0 + PN1) { j = i - PN0; srcoff = j * 4; src = w1f; dst = w1; }
    else if (i < PN0 + PN1 + PN2) { j = i - PN0 - PN1; srcoff = j * 4; src = w2f; dst = w2; }
    else if (i < PN0 + PN1 + PN2 + PN3) {
        j = i - PN0 - PN1 - PN2; srcoff = j * 4; src = wxf; dst = wx16;
        zero = ((j * 4) / Iw) >= (Rr + 2 * Nst);
    } else {
        j = i - PN0 - PN1 - PN2 - PN3; src = wdtf; dst = wdt16;
        long col4 = j & 15, row = j >> 4;
        zero = (col4 >= 12);
        srcoff = row * Rr + col4 * 4;
    }
    __half2* op = (__half2*)(dst + j * 4);
    if (zero) {
        op[0] = __half2(__half(0.f), __half(0.f));
        op[1] = __half2(__half(0.f), __half(0.f));
    } else {
        float4 v = *(const float4*)(src + srcoff);
        op[0] = __floats2half2_rn(v.x, v.y);
        op[1] = __floats2half2_rn(v.z, v.w);
    }
}

// ---------------------------------------------------------------------------
// Causal depthwise conv1d (K=4) + bias + SiLU — half2 rolling window.
// Reads fp16 hidden, writes fp16 h.
// ---------------------------------------------------------------------------
__global__ __launch_bounds__(256)
void conv_silu3(const __half* __restrict__ hid,
                const float* __restrict__ cw,
                const float* __restrict__ cb,
                __half* __restrict__ h16)
{
    const int blk = blockIdx.x;                 // Bsz * (Sl/16)
    const int b = blk / (Sl / 16);
    const int st = (blk % (Sl / 16)) * 16;
    const int rs = Iw / 2;                      // half2 row stride

#pragma unroll 1
    for (int ic = 0; ic < Iw / 512; ic++) {
        const int p = ic * 256 + threadIdx.x;   // channel pair 0..767
        const int i = p * 2;
        float4 wa = *(const float4*)(cw + (size_t)i * 4);
        float4 wb = *(const float4*)(cw + (size_t)(i + 1) * 4);
        float bx = cb[i], by = cb[i + 1];
        const __half2* base = (const __half2*)(hid + ((size_t)b * Sl + st) * Iw) + p;
        __half2* outp = (__half2*)(h16 + ((size_t)b * Sl + st) * Iw) + p;

        float2 x3, x2, x1;
        if (st > 0) {
            x3 = __half22float2(base[-3 * rs]);
            x2 = __half22float2(base[-2 * rs]);
            x1 = __half22float2(base[-1 * rs]);
        } else {
            x3 = make_float2(0.f, 0.f); x2 = x3; x1 = x3;
        }
#pragma unroll
        for (int s = 0; s < 16; s++) {
            float2 x0 = __half22float2(base[(size_t)s * rs]);
            float ax = fmaf(wa.w, x0.x, fmaf(wa.z, x1.x, fmaf(wa.y, x2.x, fmaf(wa.x, x3.x, bx))));
            float ay = fmaf(wb.w, x0.y, fmaf(wb.z, x1.y, fmaf(wb.y, x2.y, fmaf(wb.x, x3.y, by))));
            ax *= __fdividef(1.f, 1.f + __expf(-ax));
            ay *= __fdividef(1.f, 1.f + __expf(-ay));
            outp[(size_t)s * rs] = __floats2half2_rn(ax, ay);
            x3 = x2; x2 = x1; x1 = x0;
        }
    }
}

// ---------------------------------------------------------------------------
// Selective scan v4: 2 states/lane, 8 lanes/channel, 16 ch/block, 128 threads.
// ---------------------------------------------------------------------------
#define SCT 64
#define NCHK (Sl / SCT)

__global__ __launch_bounds__(128)
void scan_kernel4(const float* __restrict__ dt,
                  const __half* __restrict__ h16,
                  const float* __restrict__ ssm,
                  const float* __restrict__ gate,
                  const float* __restrict__ A_log,
                  const float* __restrict__ Dv,
                  const float* __restrict__ fg,
                  __half* __restrict__ y16)
{
    __shared__ __align__(16) float  s_dt[2][SCT][16];
    __shared__ __align__(16) float  s_g [2][SCT][16];
    __shared__ __align__(16) float  s_B [2][SCT][16];
    __shared__ __align__(16) float  s_C [2][SCT][16];
    __shared__ __align__(16) __half s_h [2][SCT][16];
    __shared__ __align__(16) float  s_y [SCT][16];
    __shared__ float s_D[16];

    const int tid = threadIdx.x;                // 0..127
    const int blk = blockIdx.x;                 // 0..191
    const int b = blk / (Iw / 16);
    const int i0 = (blk % (Iw / 16)) * 16;

    const int wid = tid >> 5;                   // 0..3
    const int lane = tid & 31;
    const int ci = wid * 4 + (lane >> 3);       // channel 0..15
    const int sl = lane & 7;                    // 2 states: sl*2, sl*2+1

    if (tid < 16) s_D[tid] = Dv[i0 + tid];

    float An0 = -__expf(A_log[(size_t)(i0 + ci) * Nst + sl * 2]);
    float An1 = -__expf(A_log[(size_t)(i0 + ci) * Nst + sl * 2 + 1]);
    float st0 = 0.f, st1 = 0.f;

    const size_t row0 = (size_t)b * Sl;

    const uint32_t a_dt = smem_u32(&s_dt[0][0][0]);
    const uint32_t a_g  = smem_u32(&s_g [0][0][0]);
    const uint32_t a_B  = smem_u32(&s_B [0][0][0]);
    const uint32_t a_C  = smem_u32(&s_C [0][0][0]);
    const uint32_t a_h  = smem_u32(&s_h [0][0][0]);
    const uint32_t stoff  = SCT * 16 * 4;
    const uint32_t stoffh = SCT * 16 * 2;

    auto issue = [&](int st, int s0) {
#pragma unroll
        for (int l = 0; l < 2; l++) {
            int v = tid + l * 128;
            int r = v >> 2, c4 = (v & 3) * 4;
            size_t grow = row0 + s0 + r;
            uint32_t off = st * stoff + (r * 16 + c4) * 4;
            cp16(a_dt + off, dt   + grow * Iw + i0 + c4);
            cp16(a_g  + off, gate + grow * Iw + i0 + c4);
            cp16(a_B  + off, ssm  + grow * (Rr + 2 * Nst) + Rr + c4);
            cp16(a_C  + off, ssm  + grow * (Rr + 2 * Nst) + Rr + Nst + c4);
        }
        {
            int v = tid;
            int r = v >> 1, c8 = (v & 1) * 8;
            size_t grow = row0 + s0 + r;
            cp16(a_h + st * stoffh + (r * 16 + c8) * 2, h16 + grow * Iw + i0 + c8);
        }
        CP_COMMIT();
    };

    issue(0, 0);

    for (int ch = 0; ch < NCHK; ch++) {
        const int st = ch & 1;
        const int s0 = ch * SCT;
        if (ch + 1 < NCHK) { issue(st ^ 1, s0 + SCT); CP_WAIT(1); }
        else               { CP_WAIT(0); }
        __syncthreads();

#pragma unroll 4
        for (int s = 0; s < SCT; s++) {
            float dtv = s_dt[st][s][ci];
            float hv  = __half2float(s_h[st][s][ci]);
            float2 Bv = *(const float2*)&s_B[st][s][sl * 2];
            float2 Cv = *(const float2*)&s_C[st][s][sl * 2];
            float dth = dtv * hv;
            st0 = fmaf(__expf(An0 * dtv), st0, dth * Bv.x);
            st1 = fmaf(__expf(An1 * dtv), st1, dth * Bv.y);
            float part = st0 * Cv.x + st1 * Cv.y;
            part += __shfl_xor_sync(0xffffffffu, part, 4);
            part += __shfl_xor_sync(0xffffffffu, part, 2);
            part += __shfl_xor_sync(0xffffffffu, part, 1);
            if (sl == 0) s_y[s][ci] = part;
        }
        __syncthreads();

#pragma unroll
        for (int k = 0; k < 8; k++) {
            int idx = tid + k * 128;
            int r = idx >> 4, c = idx & 15;
            float hv = __half2float(s_h[st][r][c]);
            float g  = s_g[st][r][c];
            float sg = g * __fdividef(1.f, 1.f + __expf(-g));
            float val = (s_y[r][c] + hv * s_D[c]) * sg;
            if (s0 + r == Sl - 1) val *= fg[i0 + c];
            y16[(row0 + s0 + r) * Iw + i0 + c] = __float2half_rn(val);
        }
        __syncthreads();
    }
}

// ---------------------------------------------------------------------------
// Launch
// ---------------------------------------------------------------------------
extern "C" void kernel_launch(void* const* d_in, const int* in_sizes, int n_in,
                              void* d_out, int out_size)
{
    const float* x          = (const float*)d_in[0];
    const float* in_proj_w  = (const float*)d_in[1];
    const float* conv_w     = (const float*)d_in[2];
    const float* conv_b     = (const float*)d_in[3];
    const float* x_proj_w   = (const float*)d_in[4];
    const float* dt_proj_w  = (const float*)d_in[5];
    const float* dt_proj_b  = (const float*)d_in[6];
    const float* A_log      = (const float*)d_in[7];
    const float* Dv         = (const float*)d_in[8];
    const float* out_proj_w = (const float*)d_in[9];
    const float* alpha      = (const float*)d_in[10];
    const float* fg         = (const float*)d_in[11];
    float* out = (float*)d_out;

    float *gate, *ssm, *dt;
    cudaGetSymbolAddress((void**)&gate, g_gate);
    cudaGetSymbolAddress((void**)&ssm,  g_ssm);
    cudaGetSymbolAddress((void**)&dt,   g_dt);

    __half *x16, *w1, *hid16, *h16, *wx16, *ts16, *wdt16, *y16, *w2;
    cudaGetSymbolAddress((void**)&x16,   g_x16);
    cudaGetSymbolAddress((void**)&w1,    g_w1);
    cudaGetSymbolAddress((void**)&hid16, g_hid16);
    cudaGetSymbolAddress((void**)&h16,   g_h16);
    cudaGetSymbolAddress((void**)&wx16,  g_wx16);
    cudaGetSymbolAddress((void**)&ts16,  g_ts16);
    cudaGetSymbolAddress((void**)&wdt16, g_wdt16);
    cudaGetSymbolAddress((void**)&y16,   g_y16);
    cudaGetSymbolAddress((void**)&w2,    g_w2);

    constexpr int SMEM128 = 3 * (A_TILE_B + 128 * STRD * 2);   // 61440
    constexpr int SMEM64  = 3 * (A_TILE_B + 64 * STRD * 2);    // 46080
    cudaFuncSetAttribute(hmma_f16<128,3>, cudaFuncAttributeMaxDynamicSharedMemorySize, SMEM128);
    cudaFuncSetAttribute(hmma_f16<64,1>,  cudaFuncAttributeMaxDynamicSharedMemorySize, SMEM64);
    cudaFuncSetAttribute(hmma_f16<64,2>,  cudaFuncAttributeMaxDynamicSharedMemorySize, SMEM64);
    cudaFuncSetAttribute(hmma_f16<64,0>,  cudaFuncAttributeMaxDynamicSharedMemorySize, SMEM64);

    // 0) all fp16 conversions in one launch
    prep_f16<<<(PTOT + 255) / 256, 256>>>(x, in_proj_w, out_proj_w, x_proj_w,
                                          dt_proj_w, x16, w1, w2, wx16, wdt16);

    // 1) in_proj (HMMA, EPI=3): hidden -> hid16 (fp16), gate -> gate (fp32)
    hmma_f16<128,3><<<dim3(TWO_I / 128, Ms / 128), 256, SMEM128>>>(
        x16, w1, gate, Ms, Dm, TWO_I, TWO_I, nullptr, nullptr, hid16);

    // 2) conv + SiLU (half2 rolling window) -> h16
    conv_silu3<<<Bsz * (Sl / 16), 256>>>(hid16, conv_w, conv_b, h16);

    // 3) x_proj (HMMA, EPI=1): ssm fp32 (cols<80) + ts16 fp16 padded
    hmma_f16<64,1><<<dim3(2, Ms / 128), 256, SMEM64>>>(
        h16, wx16, ssm, Ms, Iw, Rr + 2 * Nst, Rr + 2 * Nst, nullptr, nullptr, ts16);

    // 4) dt_proj (HMMA, EPI=2): dt = softplus(ts16 @ wdt16^T + b), alpha on last
    hmma_f16<64,2><<<dim3(Iw / 64, Ms / 128), 256, SMEM64>>>(
        ts16, wdt16, dt, Ms, 64, Iw, Iw, dt_proj_b, alpha, nullptr);

    // 5) scan v4 (reads h16/gate, emits fp16 y)
    scan_kernel4<<<(Bsz * Iw) / 16, 128>>>(dt, h16, ssm, gate, A_log, Dv, fg, y16);

    // 6) out_proj (HMMA, EPI=0): out[4096,768] = y16 @ w2^T
    hmma_f16<64,0><<<dim3(Dm / 64, Ms / 128), 256, SMEM64>>>(
        y16, w2, out, Ms, Iw, Dm, Dm, nullptr, nullptr, nullptr);
}